// round 1
// baseline (speedup 1.0000x reference)
#include <cuda_runtime.h>
#include <math.h>

#define HH 127
#define WW 127
#define CIN 64
#define CI  16
#define KS  7
#define STR 4
#define OHW 31
#define LL  961           // 31*31
#define DD  784           // 16*49
#define BB  4
#define TOPM 100

// ---------------- scratch (device globals; no allocation allowed) ------------
__device__ float d_b1[BB*CI*HH*WW];
__device__ float d_b2[BB*CI*HH*WW];
__device__ float d_b3[BB*CI*HH*WW];
__device__ float d_p1[BB*LL*DD];
__device__ float d_p2[BB*LL*DD];
__device__ float d_p3[BB*LL*DD];
__device__ float d_score[BB*LL*LL];
__device__ float d_sall[BB*DD];
__device__ float d_out16[BB*CI*HH*WW];

// ---------------- zero out16 -------------------------------------------------
__global__ void zero16_kernel() {
    int n = BB*CI*HH*WW;
    for (int i = blockIdx.x*blockDim.x + threadIdx.x; i < n; i += gridDim.x*blockDim.x)
        d_out16[i] = 0.f;
}

// ---------------- fused conv3x3 (g) + conv1x1 (theta, phi) -------------------
// grid (8,8,B), block (16,16). Channel-chunked shared tiles.
__global__ void conv_kernel(const float* __restrict__ x,
                            const float* __restrict__ g_w,  const float* __restrict__ g_b,
                            const float* __restrict__ th_w, const float* __restrict__ th_b,
                            const float* __restrict__ ph_w, const float* __restrict__ ph_b) {
    __shared__ float xs[16][18][18];
    __shared__ float gw[16][16][9];
    __shared__ float tw[16][16];
    __shared__ float pw[16][16];

    const int b  = blockIdx.z;
    const int h0 = blockIdx.y * 16, w0 = blockIdx.x * 16;
    const int tx = threadIdx.x, ty = threadIdx.y;
    const int tid = ty*16 + tx;

    float ag[16], at[16], ap[16];
    #pragma unroll
    for (int c = 0; c < 16; c++) { ag[c]=0.f; at[c]=0.f; ap[c]=0.f; }

    const float* xb = x + (size_t)b*CIN*HH*WW;

    for (int c0 = 0; c0 < CIN; c0 += 16) {
        // load input tile: 16 chans x 18x18 (halo 1)
        for (int i = tid; i < 16*18*18; i += 256) {
            int cc = i / 324;
            int rr = (i / 18) % 18;
            int col = i % 18;
            int hh = h0 - 1 + rr, ww2 = w0 - 1 + col;
            float v = 0.f;
            if (hh >= 0 && hh < HH && ww2 >= 0 && ww2 < WW)
                v = xb[(size_t)(c0+cc)*HH*WW + hh*WW + ww2];
            xs[cc][rr][col] = v;
        }
        // weights
        for (int i = tid; i < 16*16*9; i += 256) {
            int co = i / 144, ci = (i / 9) % 16, kk = i % 9;
            gw[co][ci][kk] = g_w[((co*CIN) + (c0+ci))*9 + kk];
        }
        {
            int co = tid / 16, ci = tid % 16;
            tw[co][ci] = th_w[co*CIN + c0 + ci];
            pw[co][ci] = ph_w[co*CIN + c0 + ci];
        }
        __syncthreads();

        #pragma unroll 4
        for (int ci = 0; ci < 16; ci++) {
            float n0 = xs[ci][ty+0][tx+0], n1 = xs[ci][ty+0][tx+1], n2 = xs[ci][ty+0][tx+2];
            float n3 = xs[ci][ty+1][tx+0], n4 = xs[ci][ty+1][tx+1], n5 = xs[ci][ty+1][tx+2];
            float n6 = xs[ci][ty+2][tx+0], n7 = xs[ci][ty+2][tx+1], n8 = xs[ci][ty+2][tx+2];
            #pragma unroll
            for (int co = 0; co < 16; co++) {
                const float* wv = gw[co][ci];
                float s = wv[0]*n0 + wv[1]*n1 + wv[2]*n2
                        + wv[3]*n3 + wv[4]*n4 + wv[5]*n5
                        + wv[6]*n6 + wv[7]*n7 + wv[8]*n8;
                ag[co] += s;
                at[co] += tw[co][ci] * n4;
                ap[co] += pw[co][ci] * n4;
            }
        }
        __syncthreads();
    }

    int h = h0 + ty, w = w0 + tx;
    if (h < HH && w < WW) {
        #pragma unroll
        for (int co = 0; co < 16; co++) {
            size_t o = ((size_t)(b*CI + co)*HH + h)*WW + w;
            d_b1[o] = ag[co] + g_b[co];
            d_b2[o] = at[co] + th_b[co];
            d_b3[o] = ap[co] + ph_b[co];
        }
    }
}

// ---------------- unfold: b{1,2,3} -> p{1,2,3}  [B, L, D] ---------------------
__global__ void unfold_kernel() {
    const int total = BB*LL*DD;
    int i = blockIdx.x*blockDim.x + threadIdx.x;
    if (i >= total) return;
    int d = i % DD;
    int l = (i / DD) % LL;
    int b = i / (DD*LL);
    int c = d / 49, rem = d % 49, ki = rem / 7, kj = rem % 7;
    int li = l / OHW, lj = l % OHW;
    int h = li*STR + ki, w = lj*STR + kj;
    size_t src = ((size_t)(b*CI + c)*HH + h)*WW + w;
    d_p1[i] = d_b1[src];
    d_p2[i] = d_b2[src];
    d_p3[i] = d_b3[src];
}

// ---------------- S_all[b][d] = sum_m p3[b][m][d] -----------------------------
__global__ void sall_kernel() {
    int b = blockIdx.y;
    int d = blockIdx.x*blockDim.x + threadIdx.x;
    if (d >= DD) return;
    const float* base = d_p3 + (size_t)b*LL*DD + d;
    float s = 0.f;
    for (int m = 0; m < LL; m++) s += base[(size_t)m*DD];
    d_sall[b*DD + d] = s;
}

// ---------------- score = P1 @ P2^T, per batch. 64x64 tiles, 4x4/thread -------
__global__ void score_gemm() {
    __shared__ float As[64][17];   // [m][k] padded
    __shared__ float Bs[64][17];   // [n][k] padded

    const int b  = blockIdx.z;
    const int tm = blockIdx.y * 64, tn = blockIdx.x * 64;
    const int tid = threadIdx.x;
    const int tx = tid % 16, ty = tid / 16;

    const float* A  = d_p1 + (size_t)b*LL*DD;
    const float* Bp = d_p2 + (size_t)b*LL*DD;
    float*       Sb = d_score + (size_t)b*LL*LL;

    float acc[4][4];
    #pragma unroll
    for (int i = 0; i < 4; i++)
        #pragma unroll
        for (int j = 0; j < 4; j++) acc[i][j] = 0.f;

    for (int k0 = 0; k0 < DD; k0 += 16) {
        #pragma unroll
        for (int i = tid; i < 1024; i += 256) {
            int m = i / 16, kk = i % 16;
            int gm = tm + m;
            As[m][kk] = (gm < LL) ? A [(size_t)gm*DD + k0 + kk] : 0.f;
            int gn = tn + m;
            Bs[m][kk] = (gn < LL) ? Bp[(size_t)gn*DD + k0 + kk] : 0.f;
        }
        __syncthreads();
        #pragma unroll
        for (int kk = 0; kk < 16; kk++) {
            float a[4], bb[4];
            #pragma unroll
            for (int i = 0; i < 4; i++) a[i]  = As[ty*4+i][kk];
            #pragma unroll
            for (int j = 0; j < 4; j++) bb[j] = Bs[tx*4+j][kk];
            #pragma unroll
            for (int i = 0; i < 4; i++)
                #pragma unroll
                for (int j = 0; j < 4; j++) acc[i][j] += a[i]*bb[j];
        }
        __syncthreads();
    }

    #pragma unroll
    for (int i = 0; i < 4; i++) {
        int gm = tm + ty*4 + i;
        if (gm >= LL) continue;
        #pragma unroll
        for (int j = 0; j < 4; j++) {
            int gn = tn + tx*4 + j;
            if (gn >= LL) continue;
            Sb[(size_t)gm*LL + gn] = acc[i][j];
        }
    }
}

// ---------------- per-row: top-100, softmax, sparse agg, fold(atomicAdd) ------
// grid (L, B), block 256
__global__ void topk_agg_kernel() {
    __shared__ float sval[1024];
    __shared__ int   sidx[1024];
    __shared__ float se[TOPM];
    __shared__ int   sId[TOPM];
    __shared__ float red[256];
    __shared__ float sM;

    const int l = blockIdx.x, b = blockIdx.y;
    const int tid = threadIdx.x;
    const float* row = d_score + ((size_t)b*LL + l)*LL;

    for (int i = tid; i < 1024; i += 256) {
        sval[i] = (i < LL) ? row[i] : -3.402823466e38f;
        sidx[i] = i;
    }
    __syncthreads();

    // bitonic sort, descending
    for (int k = 2; k <= 1024; k <<= 1) {
        for (int j = k >> 1; j > 0; j >>= 1) {
            #pragma unroll
            for (int t = tid; t < 512; t += 256) {
                int low = t & (j - 1);
                int i   = ((t ^ low) << 1) | low;
                int ixj = i | j;
                bool desc = ((i & k) == 0);
                float vi = sval[i], vj = sval[ixj];
                bool sw = desc ? (vi < vj) : (vi > vj);
                if (sw) {
                    sval[i] = vj; sval[ixj] = vi;
                    int tt = sidx[i]; sidx[i] = sidx[ixj]; sidx[ixj] = tt;
                }
            }
            __syncthreads();
        }
    }

    if (tid == 0) sM = fmaxf(0.f, 10.f * sval[0]);
    __syncthreads();
    const float m = sM;

    float myE = 0.f;
    if (tid < TOPM) {
        myE = expf(10.f * sval[tid] - m);
        se[tid]  = myE;
        sId[tid] = sidx[tid];
    }
    red[tid] = myE;
    __syncthreads();
    #pragma unroll
    for (int s = 128; s > 0; s >>= 1) {
        if (tid < s) red[tid] += red[tid + s];
        __syncthreads();
    }
    const float e0   = expf(-m);
    const float Z    = red[0] + (float)(LL - TOPM) * e0;
    const float invZ = 1.f / Z;

    // sparse gather-GEMM: acc[d] = sum_j (e_j - e0) * p3[idx_j][d]
    float acc0 = 0.f, acc1 = 0.f, acc2 = 0.f, acc3 = 0.f;
    const float* P3b = d_p3 + (size_t)b*LL*DD;
    for (int j = 0; j < TOPM; j++) {
        float wj = se[j] - e0;
        const float* prow = P3b + (size_t)sId[j]*DD;
        acc0 += wj * prow[tid];
        acc1 += wj * prow[tid + 256];
        acc2 += wj * prow[tid + 512];
        if (tid < DD - 768) acc3 += wj * prow[tid + 768];
    }

    const int li = l / OHW, lj = l % OHW;
    const float* sall = d_sall + b*DD;
    float accs[4] = {acc0, acc1, acc2, acc3};
    #pragma unroll
    for (int r = 0; r < 4; r++) {
        int d = tid + r*256;
        if (d >= DD) continue;
        float val = (sall[d]*e0 + accs[r]) * invZ;
        int c = d / 49, rem = d % 49, ki = rem / 7, kj = rem % 7;
        int h = li*STR + ki, w = lj*STR + kj;
        atomicAdd(&d_out16[((size_t)(b*CI + c)*HH + h)*WW + w], val);
    }
}

// ---------------- final: divide by analytic mask, restore conv ----------------
__device__ __forceinline__ int cover_count(int h) {
    int lo = h - 6; if (lo < 0) lo = 0;
    int hi = h;     if (hi > 120) hi = 120;
    return (hi >> 2) - ((lo + 3) >> 2) + 1;
}

__global__ void final_kernel(const float* __restrict__ mt_w, const float* __restrict__ mt_b,
                             const float* __restrict__ rs_w, const float* __restrict__ rs_b,
                             float* __restrict__ out) {
    __shared__ float rw[64][16];
    __shared__ float msum[16];
    __shared__ float mb[16];
    __shared__ float rb[64];

    const int tid = threadIdx.x;
    for (int i = tid; i < 1024; i += 256) rw[i/16][i%16] = rs_w[i];
    if (tid < 64) rb[tid] = rs_b[tid];
    if (tid < 16) {
        float s = 0.f;
        for (int c = 0; c < 64; c++) s += mt_w[tid*64 + c];
        msum[tid] = s;
        mb[tid]   = mt_b[tid];
    }
    __syncthreads();

    const int b = blockIdx.y;
    int pix = blockIdx.x*256 + tid;
    if (pix >= HH*WW) return;
    int h = pix / WW, w = pix % WW;
    float cnt = (float)(cover_count(h) * cover_count(w));

    float t[16];
    #pragma unroll
    for (int c = 0; c < 16; c++) {
        float v = d_out16[((size_t)(b*CI + c)*HH + h)*WW + w];
        t[c] = v / (cnt * msum[c] + mb[c] + 1e-8f);
    }
    #pragma unroll
    for (int o = 0; o < 64; o++) {
        float s = rb[o];
        #pragma unroll
        for (int c = 0; c < 16; c++) s += rw[o][c] * t[c];
        out[((size_t)(b*64 + o)*HH + h)*WW + w] = s;
    }
}

// ---------------- launch ------------------------------------------------------
extern "C" void kernel_launch(void* const* d_in, const int* in_sizes, int n_in,
                              void* d_out, int out_size) {
    const float* x    = (const float*)d_in[0];
    const float* g_w  = (const float*)d_in[1];
    const float* g_b  = (const float*)d_in[2];
    const float* th_w = (const float*)d_in[3];
    const float* th_b = (const float*)d_in[4];
    const float* ph_w = (const float*)d_in[5];
    const float* ph_b = (const float*)d_in[6];
    const float* mt_w = (const float*)d_in[7];
    const float* mt_b = (const float*)d_in[8];
    const float* rs_w = (const float*)d_in[9];
    const float* rs_b = (const float*)d_in[10];
    float* out = (float*)d_out;

    zero16_kernel<<<512, 256>>>();
    conv_kernel<<<dim3(8,8,BB), dim3(16,16)>>>(x, g_w, g_b, th_w, th_b, ph_w, ph_b);
    {
        int total = BB*LL*DD;
        unfold_kernel<<<(total + 255)/256, 256>>>();
    }
    sall_kernel<<<dim3(4, BB), 256>>>();
    score_gemm<<<dim3(16, 16, BB), 256>>>();
    topk_agg_kernel<<<dim3(LL, BB), 256>>>();
    final_kernel<<<dim3((HH*WW + 255)/256, BB), 256>>>(mt_w, mt_b, rs_w, rs_b, out);
}

// round 2
// speedup vs baseline: 1.5738x; 1.5738x over previous
#include <cuda_runtime.h>
#include <math.h>

#define HH 127
#define WW 127
#define CIN 64
#define CI  16
#define KS  7
#define STR 4
#define OHW 31
#define LL  961           // 31*31
#define DD  784           // 16*49
#define BB  4
#define TOPM 100

// ---------------- scratch (device globals; no allocation allowed) ------------
__device__ float d_b1[BB*CI*HH*WW];
__device__ float d_b2[BB*CI*HH*WW];
__device__ float d_b3[BB*CI*HH*WW];
__device__ float d_p1[BB*LL*DD];
__device__ float d_p2[BB*LL*DD];
__device__ float d_p3[BB*LL*DD];
__device__ float d_score[BB*LL*LL];
__device__ float d_sall[BB*DD];
__device__ float d_out16[BB*CI*HH*WW];

// ---------------- zero out16 + sall ------------------------------------------
__global__ void zero16_kernel() {
    int n = BB*CI*HH*WW;
    for (int i = blockIdx.x*blockDim.x + threadIdx.x; i < n; i += gridDim.x*blockDim.x)
        d_out16[i] = 0.f;
    int n2 = BB*DD;
    for (int i = blockIdx.x*blockDim.x + threadIdx.x; i < n2; i += gridDim.x*blockDim.x)
        d_sall[i] = 0.f;
}

// ---------------- fused conv3x3 (g) + conv1x1 (theta, phi) -------------------
__global__ void conv_kernel(const float* __restrict__ x,
                            const float* __restrict__ g_w,  const float* __restrict__ g_b,
                            const float* __restrict__ th_w, const float* __restrict__ th_b,
                            const float* __restrict__ ph_w, const float* __restrict__ ph_b) {
    __shared__ float xs[16][18][18];
    __shared__ float gw[16][16][9];
    __shared__ float tw[16][16];
    __shared__ float pw[16][16];

    const int b  = blockIdx.z;
    const int h0 = blockIdx.y * 16, w0 = blockIdx.x * 16;
    const int tx = threadIdx.x, ty = threadIdx.y;
    const int tid = ty*16 + tx;

    float ag[16], at[16], ap[16];
    #pragma unroll
    for (int c = 0; c < 16; c++) { ag[c]=0.f; at[c]=0.f; ap[c]=0.f; }

    const float* xb = x + (size_t)b*CIN*HH*WW;

    for (int c0 = 0; c0 < CIN; c0 += 16) {
        for (int i = tid; i < 16*18*18; i += 256) {
            int cc = i / 324;
            int rr = (i / 18) % 18;
            int col = i % 18;
            int hh = h0 - 1 + rr, ww2 = w0 - 1 + col;
            float v = 0.f;
            if (hh >= 0 && hh < HH && ww2 >= 0 && ww2 < WW)
                v = xb[(size_t)(c0+cc)*HH*WW + hh*WW + ww2];
            xs[cc][rr][col] = v;
        }
        for (int i = tid; i < 16*16*9; i += 256) {
            int co = i / 144, ci = (i / 9) % 16, kk = i % 9;
            gw[co][ci][kk] = g_w[((co*CIN) + (c0+ci))*9 + kk];
        }
        {
            int co = tid / 16, ci = tid % 16;
            tw[co][ci] = th_w[co*CIN + c0 + ci];
            pw[co][ci] = ph_w[co*CIN + c0 + ci];
        }
        __syncthreads();

        #pragma unroll 4
        for (int ci = 0; ci < 16; ci++) {
            float n0 = xs[ci][ty+0][tx+0], n1 = xs[ci][ty+0][tx+1], n2 = xs[ci][ty+0][tx+2];
            float n3 = xs[ci][ty+1][tx+0], n4 = xs[ci][ty+1][tx+1], n5 = xs[ci][ty+1][tx+2];
            float n6 = xs[ci][ty+2][tx+0], n7 = xs[ci][ty+2][tx+1], n8 = xs[ci][ty+2][tx+2];
            #pragma unroll
            for (int co = 0; co < 16; co++) {
                const float* wv = gw[co][ci];
                float s = wv[0]*n0 + wv[1]*n1 + wv[2]*n2
                        + wv[3]*n3 + wv[4]*n4 + wv[5]*n5
                        + wv[6]*n6 + wv[7]*n7 + wv[8]*n8;
                ag[co] += s;
                at[co] += tw[co][ci] * n4;
                ap[co] += pw[co][ci] * n4;
            }
        }
        __syncthreads();
    }

    int h = h0 + ty, w = w0 + tx;
    if (h < HH && w < WW) {
        #pragma unroll
        for (int co = 0; co < 16; co++) {
            size_t o = ((size_t)(b*CI + co)*HH + h)*WW + w;
            d_b1[o] = ag[co] + g_b[co];
            d_b2[o] = at[co] + th_b[co];
            d_b3[o] = ap[co] + ph_b[co];
        }
    }
}

// ---------------- unfold --------------------------------------------------
__global__ void unfold_kernel() {
    const int total = BB*LL*DD;
    int i = blockIdx.x*blockDim.x + threadIdx.x;
    if (i >= total) return;
    int d = i % DD;
    int l = (i / DD) % LL;
    int b = i / (DD*LL);
    int c = d / 49, rem = d % 49, ki = rem / 7, kj = rem % 7;
    int li = l / OHW, lj = l % OHW;
    int h = li*STR + ki, w = lj*STR + kj;
    size_t src = ((size_t)(b*CI + c)*HH + h)*WW + w;
    d_p1[i] = d_b1[src];
    d_p2[i] = d_b2[src];
    d_p3[i] = d_b3[src];
}

// ---------------- S_all: split-m with atomics ---------------------------------
__global__ void sall_kernel() {
    int b = blockIdx.z;
    int d = blockIdx.x*blockDim.x + threadIdx.x;
    if (d >= DD) return;
    int m0 = blockIdx.y * 121;
    int m1 = m0 + 121; if (m1 > LL) m1 = LL;
    const float* base = d_p3 + (size_t)b*LL*DD + d;
    float s = 0.f;
    for (int m = m0; m < m1; m++) s += base[(size_t)m*DD];
    atomicAdd(&d_sall[b*DD + d], s);
}

// ---------------- score = P1 @ P2^T: 128x128 tiles, FFMA2 (f32x2) -------------
#define FMA2(d, a, b) asm volatile("fma.rn.f32x2 %0, %1, %2, %0;" : "+l"(d) : "l"(a), "l"(b))
__device__ __forceinline__ unsigned long long dupf(float v) {
    unsigned long long r;
    asm volatile("mov.b64 %0, {%1, %1};" : "=l"(r) : "f"(v));
    return r;
}

__global__ void __launch_bounds__(256, 2) score_gemm() {
    __shared__ __align__(16) float As[2][8][132];
    __shared__ __align__(16) float Bs[2][8][132];

    const int b  = blockIdx.z;
    const int tm = blockIdx.y * 128, tn = blockIdx.x * 128;
    const int tid = threadIdx.x;
    const int tx = tid % 16, ty = tid / 16;

    const float* A  = d_p1 + (size_t)b*LL*DD;
    const float* Bp = d_p2 + (size_t)b*LL*DD;
    float*       Sb = d_score + (size_t)b*LL*LL;

    // load mapping: thread -> (row = tid>>1, kpart = (tid&1)*4)
    const int lrow = tid >> 1;
    const int lkp  = (tid & 1) * 4;
    const int gmA = tm + lrow;
    const int gnB = tn + lrow;
    const bool vA = (gmA < LL);
    const bool vB = (gnB < LL);
    const float* Aptr = A  + (size_t)(vA ? gmA : 0)*DD + lkp;
    const float* Bptr = Bp + (size_t)(vB ? gnB : 0)*DD + lkp;

    unsigned long long acc[8][4];
    #pragma unroll
    for (int i = 0; i < 8; i++)
        #pragma unroll
        for (int j = 0; j < 4; j++) acc[i][j] = 0ull;

    // prologue: load tile 0
    {
        float4 a4 = vA ? *(const float4*)(Aptr) : make_float4(0,0,0,0);
        float4 b4 = vB ? *(const float4*)(Bptr) : make_float4(0,0,0,0);
        As[0][lkp+0][lrow] = a4.x; As[0][lkp+1][lrow] = a4.y;
        As[0][lkp+2][lrow] = a4.z; As[0][lkp+3][lrow] = a4.w;
        Bs[0][lkp+0][lrow] = b4.x; Bs[0][lkp+1][lrow] = b4.y;
        Bs[0][lkp+2][lrow] = b4.z; Bs[0][lkp+3][lrow] = b4.w;
    }
    __syncthreads();

    const int NT = DD / 8;  // 98
    int buf = 0;
    for (int kt = 0; kt < NT; kt++) {
        float4 pa, pb;
        const bool more = (kt + 1 < NT);
        if (more) {
            int ko = (kt+1)*8;
            pa = vA ? *(const float4*)(Aptr + ko) : make_float4(0,0,0,0);
            pb = vB ? *(const float4*)(Bptr + ko) : make_float4(0,0,0,0);
        }

        #pragma unroll
        for (int kk = 0; kk < 8; kk++) {
            const float* arow = &As[buf][kk][ty*8];
            unsigned long long ap[8];
            #pragma unroll
            for (int i = 0; i < 8; i++) ap[i] = dupf(arow[i]);
            const unsigned long long* brow =
                reinterpret_cast<const unsigned long long*>(&Bs[buf][kk][0]) + tx*4;
            unsigned long long bp[4];
            #pragma unroll
            for (int j = 0; j < 4; j++) bp[j] = brow[j];
            #pragma unroll
            for (int i = 0; i < 8; i++)
                #pragma unroll
                for (int j = 0; j < 4; j++)
                    FMA2(acc[i][j], ap[i], bp[j]);
        }

        if (more) {
            int nb = buf ^ 1;
            As[nb][lkp+0][lrow] = pa.x; As[nb][lkp+1][lrow] = pa.y;
            As[nb][lkp+2][lrow] = pa.z; As[nb][lkp+3][lrow] = pa.w;
            Bs[nb][lkp+0][lrow] = pb.x; Bs[nb][lkp+1][lrow] = pb.y;
            Bs[nb][lkp+2][lrow] = pb.z; Bs[nb][lkp+3][lrow] = pb.w;
        }
        __syncthreads();
        buf ^= 1;
    }

    #pragma unroll
    for (int i = 0; i < 8; i++) {
        int gm = tm + ty*8 + i;
        if (gm >= LL) continue;
        float* orow = Sb + (size_t)gm*LL + tn + tx*8;
        #pragma unroll
        for (int j = 0; j < 4; j++) {
            float lo, hi;
            asm volatile("mov.b64 {%0, %1}, %2;" : "=f"(lo), "=f"(hi) : "l"(acc[i][j]));
            int gn0 = tn + tx*8 + 2*j;
            if (gn0 < LL)     orow[2*j]     = lo;
            if (gn0 + 1 < LL) orow[2*j + 1] = hi;
        }
    }
}

// ---------------- monotonic float<->key transform -----------------------------
__device__ __forceinline__ unsigned fkey(float f) {
    unsigned u = __float_as_uint(f);
    return u ^ (((int)u >> 31) | 0x80000000u);
}
__device__ __forceinline__ float funkey(unsigned k) {
    unsigned u = (k & 0x80000000u) ? (k ^ 0x80000000u) : ~k;
    return __uint_as_float(u);
}

// ---------------- per-row: radix-select top-100, softmax, gather, fold --------
__global__ void __launch_bounds__(256) topk_agg_kernel() {
    __shared__ unsigned keys[LL];
    __shared__ int hist[256];
    __shared__ int scn[256];
    __shared__ float red[256];
    __shared__ unsigned sKey[TOPM];
    __shared__ int sId[TOPM];
    __shared__ float se[TOPM];
    __shared__ unsigned prefix;
    __shared__ int kneed;
    __shared__ int cg, ce;

    const int l = blockIdx.x, b = blockIdx.y;
    const int tid = threadIdx.x;
    const float* row = d_score + ((size_t)b*LL + l)*LL;

    // load + transform + max-reduce
    unsigned kmax = 0;
    #pragma unroll
    for (int r = 0; r < 4; r++) {
        int i = tid + r*256;
        if (i < LL) {
            unsigned k = fkey(row[i]);
            keys[i] = k;
            kmax = max(kmax, k);
        }
    }
    red[tid] = __uint_as_float(kmax);   // reuse as uint storage (bit tricks ok since compare via uint)
    if (tid == 0) { prefix = 0; kneed = TOPM; cg = 0; ce = 0; }
    __syncthreads();
    // max over keys via uint compare in shared
    #pragma unroll
    for (int s = 128; s > 0; s >>= 1) {
        if (tid < s) {
            unsigned a = __float_as_uint(red[tid]);
            unsigned c = __float_as_uint(red[tid + s]);
            red[tid] = __uint_as_float(a > c ? a : c);
        }
        __syncthreads();
    }
    const float vmax = funkey(__float_as_uint(red[0]));
    const float m = fmaxf(0.f, 10.f * vmax);
    __syncthreads();

    // 4-pass radix select (MSB -> LSB) for the exact 100th-largest key
    #pragma unroll
    for (int pass = 3; pass >= 0; pass--) {
        const int shift = pass * 8;
        const unsigned pm = (pass == 3) ? 0u : (0xFFFFFFFFu << (shift + 8));
        hist[tid] = 0;
        __syncthreads();
        unsigned pref = prefix;
        #pragma unroll
        for (int r = 0; r < 4; r++) {
            int i = tid + r*256;
            if (i < LL) {
                unsigned k = keys[i];
                if ((k & pm) == (pref & pm))
                    atomicAdd(&hist[(k >> shift) & 255], 1);
            }
        }
        __syncthreads();
        scn[tid] = hist[tid];
        __syncthreads();
        #pragma unroll
        for (int off = 1; off < 256; off <<= 1) {
            int v = (tid + off < 256) ? scn[tid + off] : 0;
            __syncthreads();
            scn[tid] += v;
            __syncthreads();
        }
        int kc = kneed;
        int gt = (tid < 255) ? scn[tid + 1] : 0;
        __syncthreads();
        if (scn[tid] >= kc && gt < kc) {
            prefix |= ((unsigned)tid) << shift;
            kneed = kc - gt;
        }
        __syncthreads();
    }

    const unsigned T = prefix;
    const int nTies = kneed;            // how many == T to take
    const int nGt = TOPM - nTies;       // count strictly greater than T

    // collect
    #pragma unroll
    for (int r = 0; r < 4; r++) {
        int i = tid + r*256;
        if (i < LL) {
            unsigned k = keys[i];
            if (k > T) {
                int p = atomicAdd(&cg, 1);
                sKey[p] = k; sId[p] = i;
            } else if (k == T) {
                int q = atomicAdd(&ce, 1);
                if (q < nTies) {
                    sKey[nGt + q] = k; sId[nGt + q] = i;
                }
            }
        }
    }
    __syncthreads();

    // softmax weights over the 100 selected
    float myE = 0.f;
    if (tid < TOPM) {
        myE = expf(10.f * funkey(sKey[tid]) - m);
        se[tid] = myE;
    }
    red[tid] = myE;
    __syncthreads();
    #pragma unroll
    for (int s = 128; s > 0; s >>= 1) {
        if (tid < s) red[tid] += red[tid + s];
        __syncthreads();
    }
    const float e0   = expf(-m);
    const float Z    = red[0] + (float)(LL - TOPM) * e0;
    const float invZ = 1.f / Z;

    // gather-GEMM (float4, threads 0..195)
    float4 acc = make_float4(0.f, 0.f, 0.f, 0.f);
    const float* P3b = d_p3 + (size_t)b*LL*DD;
    if (tid < 196) {
        #pragma unroll 4
        for (int j = 0; j < TOPM; j++) {
            float wj = se[j] - e0;
            const float4* pr = (const float4*)(P3b + (size_t)sId[j]*DD) + tid;
            float4 p = *pr;
            acc.x += wj * p.x; acc.y += wj * p.y;
            acc.z += wj * p.z; acc.w += wj * p.w;
        }

        const int li = l / OHW, lj = l % OHW;
        const float* sall = d_sall + b*DD;
        float a4[4] = {acc.x, acc.y, acc.z, acc.w};
        #pragma unroll
        for (int q = 0; q < 4; q++) {
            int d = 4*tid + q;
            float val = (sall[d]*e0 + a4[q]) * invZ;
            int c = d / 49, rem = d % 49, ki = rem / 7, kj = rem % 7;
            int h = li*STR + ki, w = lj*STR + kj;
            atomicAdd(&d_out16[((size_t)(b*CI + c)*HH + h)*WW + w], val);
        }
    }
}

// ---------------- final: divide by analytic mask, restore conv ----------------
__device__ __forceinline__ int cover_count(int h) {
    int lo = h - 6; if (lo < 0) lo = 0;
    int hi = h;     if (hi > 120) hi = 120;
    return (hi >> 2) - ((lo + 3) >> 2) + 1;
}

__global__ void final_kernel(const float* __restrict__ mt_w, const float* __restrict__ mt_b,
                             const float* __restrict__ rs_w, const float* __restrict__ rs_b,
                             float* __restrict__ out) {
    __shared__ float rw[64][16];
    __shared__ float msum[16];
    __shared__ float mb[16];
    __shared__ float rb[64];

    const int tid = threadIdx.x;
    for (int i = tid; i < 1024; i += 256) rw[i/16][i%16] = rs_w[i];
    if (tid < 64) rb[tid] = rs_b[tid];
    if (tid < 16) {
        float s = 0.f;
        for (int c = 0; c < 64; c++) s += mt_w[tid*64 + c];
        msum[tid] = s;
        mb[tid]   = mt_b[tid];
    }
    __syncthreads();

    const int b = blockIdx.y;
    int pix = blockIdx.x*256 + tid;
    if (pix >= HH*WW) return;
    int h = pix / WW, w = pix % WW;
    float cnt = (float)(cover_count(h) * cover_count(w));

    float t[16];
    #pragma unroll
    for (int c = 0; c < 16; c++) {
        float v = d_out16[((size_t)(b*CI + c)*HH + h)*WW + w];
        t[c] = v / (cnt * msum[c] + mb[c] + 1e-8f);
    }
    #pragma unroll
    for (int o = 0; o < 64; o++) {
        float s = rb[o];
        #pragma unroll
        for (int c = 0; c < 16; c++) s += rw[o][c] * t[c];
        out[((size_t)(b*64 + o)*HH + h)*WW + w] = s;
    }
}

// ---------------- launch ------------------------------------------------------
extern "C" void kernel_launch(void* const* d_in, const int* in_sizes, int n_in,
                              void* d_out, int out_size) {
    const float* x    = (const float*)d_in[0];
    const float* g_w  = (const float*)d_in[1];
    const float* g_b  = (const float*)d_in[2];
    const float* th_w = (const float*)d_in[3];
    const float* th_b = (const float*)d_in[4];
    const float* ph_w = (const float*)d_in[5];
    const float* ph_b = (const float*)d_in[6];
    const float* mt_w = (const float*)d_in[7];
    const float* mt_b = (const float*)d_in[8];
    const float* rs_w = (const float*)d_in[9];
    const float* rs_b = (const float*)d_in[10];
    float* out = (float*)d_out;

    zero16_kernel<<<512, 256>>>();
    conv_kernel<<<dim3(8,8,BB), dim3(16,16)>>>(x, g_w, g_b, th_w, th_b, ph_w, ph_b);
    {
        int total = BB*LL*DD;
        unfold_kernel<<<(total + 255)/256, 256>>>();
    }
    sall_kernel<<<dim3(4, 8, BB), 256>>>();
    score_gemm<<<dim3(8, 8, BB), 256>>>();
    topk_agg_kernel<<<dim3(LL, BB), 256>>>();
    final_kernel<<<dim3((HH*WW + 255)/256, BB), 256>>>(mt_w, mt_b, rs_w, rs_b, out);
}

// round 4
// speedup vs baseline: 2.3086x; 1.4669x over previous
#include <cuda_runtime.h>
#include <cuda_bf16.h>
#include <cuda_fp16.h>
#include <math.h>

#define HH 127
#define WW 127
#define CIN 64
#define CI  16
#define STR 4
#define OHW 31
#define LL  961           // 31*31
#define DD  784           // 16*49
#define BB  4
#define TOPM 100
#define LP 1024           // padded L
#define KP 832            // padded K (row stride of bf16 buffers)
#define NST 25            // 25 k-stages of 32 cover 800 >= 784
#define SP 964            // score row pitch (16B-aligned rows)

#define OPB 10240         // one operand tile in smem: 128 rows * 80B
#define STAGE_B (4*OPB)   // Ah, Al, Bh, Bl

// ---------------- scratch (device globals; no allocation allowed) ------------
__device__ float d_b1[BB*CI*HH*WW];
__device__ float d_b2[BB*CI*HH*WW];
__device__ float d_b3[BB*CI*HH*WW];
__device__ __nv_bfloat16 d_p1h[BB*LP*KP];
__device__ __nv_bfloat16 d_p1l[BB*LP*KP];
__device__ __nv_bfloat16 d_p2h[BB*LP*KP];
__device__ __nv_bfloat16 d_p2l[BB*LP*KP];
__device__ float  d_p3 [BB*LL*DD];
__device__ __half d_p3h[BB*LL*DD];
__device__ float d_score[BB*LL*SP];
__device__ float d_sall[BB*DD];
__device__ float d_out16[BB*CI*HH*WW];

// ---------------- PTX helpers --------------------------------------------------
__device__ __forceinline__ unsigned smem_u32(const void* p) {
    unsigned a;
    asm("{ .reg .u64 t; cvta.to.shared.u64 t, %1; cvt.u32.u64 %0, t; }" : "=r"(a) : "l"(p));
    return a;
}
__device__ __forceinline__ void cpa16(unsigned sdst, const void* gsrc) {
    asm volatile("cp.async.cg.shared.global [%0], [%1], 16;" :: "r"(sdst), "l"(gsrc));
}
#define CP_COMMIT() asm volatile("cp.async.commit_group;" ::: "memory")
#define CP_WAIT1()  asm volatile("cp.async.wait_group 1;" ::: "memory")

#define LDSM4(R, addr) \
    asm volatile("ldmatrix.sync.aligned.m8n8.x4.shared.b16 {%0,%1,%2,%3}, [%4];" \
        : "=r"((R)[0]),"=r"((R)[1]),"=r"((R)[2]),"=r"((R)[3]) : "r"(addr))

#define MMA16816(D, A, B0, B1) \
    asm volatile("mma.sync.aligned.m16n8k16.row.col.f32.bf16.bf16.f32 " \
        "{%0,%1,%2,%3}, {%4,%5,%6,%7}, {%8,%9}, {%0,%1,%2,%3};" \
        : "+f"((D)[0]),"+f"((D)[1]),"+f"((D)[2]),"+f"((D)[3]) \
        : "r"((A)[0]),"r"((A)[1]),"r"((A)[2]),"r"((A)[3]), "r"(B0),"r"(B1))

// ---------------- zero out16 + sall ------------------------------------------
__global__ void zero16_kernel() {
    int n = BB*CI*HH*WW;
    for (int i = blockIdx.x*blockDim.x + threadIdx.x; i < n; i += gridDim.x*blockDim.x)
        d_out16[i] = 0.f;
    int n2 = BB*DD;
    for (int i = blockIdx.x*blockDim.x + threadIdx.x; i < n2; i += gridDim.x*blockDim.x)
        d_sall[i] = 0.f;
}

// ---------------- fused conv3x3 (g) + conv1x1 (theta, phi) -------------------
__global__ void conv_kernel(const float* __restrict__ x,
                            const float* __restrict__ g_w,  const float* __restrict__ g_b,
                            const float* __restrict__ th_w, const float* __restrict__ th_b,
                            const float* __restrict__ ph_w, const float* __restrict__ ph_b) {
    __shared__ float xs[16][18][18];
    __shared__ float gw[16][16][9];
    __shared__ float tw[16][16];
    __shared__ float pw[16][16];

    const int b  = blockIdx.z;
    const int h0 = blockIdx.y * 16, w0 = blockIdx.x * 16;
    const int tx = threadIdx.x, ty = threadIdx.y;
    const int tid = ty*16 + tx;

    float ag[16], at[16], ap[16];
    #pragma unroll
    for (int c = 0; c < 16; c++) { ag[c]=0.f; at[c]=0.f; ap[c]=0.f; }

    const float* xb = x + (size_t)b*CIN*HH*WW;

    for (int c0 = 0; c0 < CIN; c0 += 16) {
        for (int i = tid; i < 16*18*18; i += 256) {
            int cc = i / 324;
            int rr = (i / 18) % 18;
            int col = i % 18;
            int hh = h0 - 1 + rr, ww2 = w0 - 1 + col;
            float v = 0.f;
            if (hh >= 0 && hh < HH && ww2 >= 0 && ww2 < WW)
                v = xb[(size_t)(c0+cc)*HH*WW + hh*WW + ww2];
            xs[cc][rr][col] = v;
        }
        for (int i = tid; i < 16*16*9; i += 256) {
            int co = i / 144, ci = (i / 9) % 16, kk = i % 9;
            gw[co][ci][kk] = g_w[((co*CIN) + (c0+ci))*9 + kk];
        }
        {
            int co = tid / 16, ci = tid % 16;
            tw[co][ci] = th_w[co*CIN + c0 + ci];
            pw[co][ci] = ph_w[co*CIN + c0 + ci];
        }
        __syncthreads();

        #pragma unroll 4
        for (int ci = 0; ci < 16; ci++) {
            float n0 = xs[ci][ty+0][tx+0], n1 = xs[ci][ty+0][tx+1], n2 = xs[ci][ty+0][tx+2];
            float n3 = xs[ci][ty+1][tx+0], n4 = xs[ci][ty+1][tx+1], n5 = xs[ci][ty+1][tx+2];
            float n6 = xs[ci][ty+2][tx+0], n7 = xs[ci][ty+2][tx+1], n8 = xs[ci][ty+2][tx+2];
            #pragma unroll
            for (int co = 0; co < 16; co++) {
                const float* wv = gw[co][ci];
                float s = wv[0]*n0 + wv[1]*n1 + wv[2]*n2
                        + wv[3]*n3 + wv[4]*n4 + wv[5]*n5
                        + wv[6]*n6 + wv[7]*n7 + wv[8]*n8;
                ag[co] += s;
                at[co] += tw[co][ci] * n4;
                ap[co] += pw[co][ci] * n4;
            }
        }
        __syncthreads();
    }

    int h = h0 + ty, w = w0 + tx;
    if (h < HH && w < WW) {
        #pragma unroll
        for (int co = 0; co < 16; co++) {
            size_t o = ((size_t)(b*CI + co)*HH + h)*WW + w;
            d_b1[o] = ag[co] + g_b[co];
            d_b2[o] = at[co] + th_b[co];
            d_b3[o] = ap[co] + ph_b[co];
        }
    }
}

// ---------------- unfold + bf16 split + fp16 copy + zero pads -----------------
__global__ void unfold_kernel() {
    const int total = BB*LP*KP;
    int i = blockIdx.x*blockDim.x + threadIdx.x;
    if (i >= total) return;
    int k = i % KP;
    int l = (i / KP) % LP;
    int b = i / (KP*LP);
    if (l < LL && k < DD) {
        int c = k / 49, rem = k % 49, ki = rem / 7, kj = rem % 7;
        int li = l / OHW, lj = l % OHW;
        int h = li*STR + ki, w = lj*STR + kj;
        size_t src = ((size_t)(b*CI + c)*HH + h)*WW + w;
        float v1 = d_b1[src], v2 = d_b2[src], v3 = d_b3[src];
        __nv_bfloat16 h1 = __float2bfloat16(v1);
        d_p1h[i] = h1;
        d_p1l[i] = __float2bfloat16(v1 - __bfloat162float(h1));
        __nv_bfloat16 h2 = __float2bfloat16(v2);
        d_p2h[i] = h2;
        d_p2l[i] = __float2bfloat16(v2 - __bfloat162float(h2));
        size_t pidx = ((size_t)b*LL + l)*DD + k;
        d_p3[pidx]  = v3;
        d_p3h[pidx] = __float2half_rn(v3);
    } else {
        __nv_bfloat16 z = __float2bfloat16(0.f);
        d_p1h[i] = z; d_p1l[i] = z; d_p2h[i] = z; d_p2l[i] = z;
    }
}

// ---------------- S_all: split-m with atomics ---------------------------------
__global__ void sall_kernel() {
    int b = blockIdx.z;
    int d = blockIdx.x*blockDim.x + threadIdx.x;
    if (d >= DD) return;
    int m0 = blockIdx.y * 61;
    int m1 = m0 + 61; if (m1 > LL) m1 = LL;
    const float* base = d_p3 + (size_t)b*LL*DD + d;
    float s = 0.f;
    #pragma unroll 4
    for (int m = m0; m < m1; m++) s += base[(size_t)m*DD];
    atomicAdd(&d_sall[b*DD + d], s);
}

// ---------------- score = P1 @ P2^T via mma.sync bf16 3-split, fp32 accum -----
// grid (8,8,B), 256 threads (8 warps, 2x4). 128x128 tile, K staged at 32,
// 2-deep cp.async pipeline. smem rows pitched 80B -> conflict-free ldmatrix.
__global__ void __launch_bounds__(256) score_gemm_mma() {
    extern __shared__ char smem[];
    const unsigned sb = smem_u32(smem);
    const int b = blockIdx.z;
    const int tmb = blockIdx.y * 128, tnb = blockIdx.x * 128;
    const int tid = threadIdx.x;
    const int wid = tid >> 5, lane = tid & 31;
    const int warp_m = wid >> 2;   // 0..1  -> m offset *64
    const int warp_n = wid & 3;    // 0..3  -> n offset *32

    const char* gops[4] = {
        (const char*)(d_p1h + (size_t)b*LP*KP + (size_t)tmb*KP),
        (const char*)(d_p1l + (size_t)b*LP*KP + (size_t)tmb*KP),
        (const char*)(d_p2h + (size_t)b*LP*KP + (size_t)tnb*KP),
        (const char*)(d_p2l + (size_t)b*LP*KP + (size_t)tnb*KP)
    };

    // fragment smem offsets (lane-dependent, stage/op/k16 added at use)
    const unsigned aoff = (unsigned)((warp_m*64 + (lane & 15))*80 + (lane >> 4)*16);
    const unsigned boff = (unsigned)((warp_n*32 + (lane & 7) + ((lane >> 4) << 3))*80
                                     + ((lane >> 3) & 1)*16);

    float acc[4][4][4];
    #pragma unroll
    for (int i = 0; i < 4; i++)
        #pragma unroll
        for (int j = 0; j < 4; j++)
            #pragma unroll
            for (int q = 0; q < 4; q++) acc[i][j][q] = 0.f;

    // stage loader: 2048 16B chunks, 8 per thread
    #define LOAD_STAGE(s) do { \
        unsigned st_ = sb + ((s) & 1)*STAGE_B; \
        _Pragma("unroll") \
        for (int j_ = 0; j_ < 8; j_++) { \
            int idx_ = j_*256 + tid; \
            int op_ = idx_ >> 9, row_ = (idx_ >> 2) & 127, c_ = idx_ & 3; \
            cpa16(st_ + op_*OPB + row_*80 + c_*16, \
                  gops[op_] + (size_t)row_*(KP*2) + (size_t)(s)*64 + c_*16); \
        } \
    } while (0)

    LOAD_STAGE(0); CP_COMMIT();
    LOAD_STAGE(1); CP_COMMIT();

    for (int s = 0; s < NST; s++) {
        CP_WAIT1();
        __syncthreads();
        const unsigned stg = sb + (s & 1)*STAGE_B;

        #pragma unroll
        for (int k16 = 0; k16 < 2; k16++) {
            unsigned bh[8], bl[8];
            const unsigned bbase = stg + 2*OPB + boff + k16*32;
            LDSM4(bh + 0, bbase);
            LDSM4(bh + 4, bbase + 16*80);
            LDSM4(bl + 0, bbase + OPB);
            LDSM4(bl + 4, bbase + OPB + 16*80);

            #pragma unroll
            for (int mt = 0; mt < 4; mt++) {
                unsigned ah[4], al[4];
                const unsigned abase = stg + aoff + mt*(16*80) + k16*32;
                LDSM4(ah, abase);
                LDSM4(al, abase + OPB);
                #pragma unroll
                for (int nt = 0; nt < 4; nt++) {
                    MMA16816(acc[mt][nt], ah, bh[2*nt], bh[2*nt+1]);
                    MMA16816(acc[mt][nt], ah, bl[2*nt], bl[2*nt+1]);
                    MMA16816(acc[mt][nt], al, bh[2*nt], bh[2*nt+1]);
                }
            }
        }
        __syncthreads();
        if (s + 2 < NST) LOAD_STAGE(s + 2);
        CP_COMMIT();
    }

    // epilogue: scatter accumulators (C layout: c0 row=lane/4 col=(lane%4)*2,
    // c1 col+1, c2 row+8, c3 row+8 col+1)
    #pragma unroll
    for (int mt = 0; mt < 4; mt++) {
        const int gm0 = tmb + warp_m*64 + mt*16 + (lane >> 2);
        #pragma unroll
        for (int nt = 0; nt < 4; nt++) {
            const int gn = tnb + warp_n*32 + nt*8 + (lane & 3)*2;
            const float* C = acc[mt][nt];
            if (gn < LL) {
                const bool two = (gn + 1 < LL);
                if (gm0 < LL) {
                    float* r = d_score + ((size_t)b*LL + gm0)*SP + gn;
                    r[0] = C[0];
                    if (two) r[1] = C[1];
                }
                if (gm0 + 8 < LL) {
                    float* r = d_score + ((size_t)b*LL + gm0 + 8)*SP + gn;
                    r[0] = C[2];
                    if (two) r[1] = C[3];
                }
            }
        }
    }
    #undef LOAD_STAGE
}

// ---------------- monotonic float<->key transform -----------------------------
__device__ __forceinline__ unsigned fkey(float f) {
    unsigned u = __float_as_uint(f);
    return u ^ (((int)u >> 31) | 0x80000000u);
}
__device__ __forceinline__ float funkey(unsigned k) {
    unsigned u = (k & 0x80000000u) ? (k ^ 0x80000000u) : ~k;
    return __uint_as_float(u);
}

// ---------------- per-row: radix-select top-100, softmax, gather, fold --------
__global__ void __launch_bounds__(256) topk_agg_kernel() {
    __shared__ unsigned keys[LL];
    __shared__ int hist[256];
    __shared__ int scn[256];
    __shared__ float red[256];
    __shared__ unsigned sKey[TOPM];
    __shared__ int sId[TOPM];
    __shared__ float se[TOPM];
    __shared__ unsigned prefix;
    __shared__ int kneed;
    __shared__ int cg, ce;

    const int l = blockIdx.x, b = blockIdx.y;
    const int tid = threadIdx.x;
    const float* row = d_score + ((size_t)b*LL + l)*SP;

    unsigned kmax = 0;
    #pragma unroll
    for (int r = 0; r < 4; r++) {
        int i = tid + r*256;
        if (i < LL) {
            unsigned k = fkey(row[i]);
            keys[i] = k;
            kmax = max(kmax, k);
        }
    }
    red[tid] = __uint_as_float(kmax);
    if (tid == 0) { prefix = 0; kneed = TOPM; cg = 0; ce = 0; }
    __syncthreads();
    #pragma unroll
    for (int s = 128; s > 0; s >>= 1) {
        if (tid < s) {
            unsigned a = __float_as_uint(red[tid]);
            unsigned c = __float_as_uint(red[tid + s]);
            red[tid] = __uint_as_float(a > c ? a : c);
        }
        __syncthreads();
    }
    const float vmax = funkey(__float_as_uint(red[0]));
    const float m = fmaxf(0.f, 10.f * vmax);
    __syncthreads();

    #pragma unroll
    for (int pass = 3; pass >= 0; pass--) {
        const int shift = pass * 8;
        const unsigned pm = (pass == 3) ? 0u : (0xFFFFFFFFu << (shift + 8));
        hist[tid] = 0;
        __syncthreads();
        unsigned pref = prefix;
        #pragma unroll
        for (int r = 0; r < 4; r++) {
            int i = tid + r*256;
            if (i < LL) {
                unsigned k = keys[i];
                if ((k & pm) == (pref & pm))
                    atomicAdd(&hist[(k >> shift) & 255], 1);
            }
        }
        __syncthreads();
        scn[tid] = hist[tid];
        __syncthreads();
        #pragma unroll
        for (int off = 1; off < 256; off <<= 1) {
            int v = (tid + off < 256) ? scn[tid + off] : 0;
            __syncthreads();
            scn[tid] += v;
            __syncthreads();
        }
        int kc = kneed;
        int gt = (tid < 255) ? scn[tid + 1] : 0;
        __syncthreads();
        if (scn[tid] >= kc && gt < kc) {
            prefix |= ((unsigned)tid) << shift;
            kneed = kc - gt;
        }
        __syncthreads();
    }

    const unsigned T = prefix;
    const int nTies = kneed;
    const int nGt = TOPM - nTies;

    #pragma unroll
    for (int r = 0; r < 4; r++) {
        int i = tid + r*256;
        if (i < LL) {
            unsigned k = keys[i];
            if (k > T) {
                int p = atomicAdd(&cg, 1);
                sKey[p] = k; sId[p] = i;
            } else if (k == T) {
                int q = atomicAdd(&ce, 1);
                if (q < nTies) {
                    sKey[nGt + q] = k; sId[nGt + q] = i;
                }
            }
        }
    }
    __syncthreads();

    float myE = 0.f;
    if (tid < TOPM) {
        myE = expf(10.f * funkey(sKey[tid]) - m);
        se[tid] = myE;
    }
    red[tid] = myE;
    __syncthreads();
    #pragma unroll
    for (int s = 128; s > 0; s >>= 1) {
        if (tid < s) red[tid] += red[tid + s];
        __syncthreads();
    }
    const float e0   = expf(-m);
    const float Z    = red[0] + (float)(LL - TOPM) * e0;
    const float invZ = 1.f / Z;

    // gather-GEMM over fp16 p3 (threads 0..97, 8 halves each = 16B)
    if (tid < 98) {
        float acc[8];
        #pragma unroll
        for (int q = 0; q < 8; q++) acc[q] = 0.f;
        const __half* P3b = d_p3h + (size_t)b*LL*DD;
        #pragma unroll 2
        for (int j = 0; j < TOPM; j++) {
            float wj = se[j] - e0;
            uint4 v = *((const uint4*)(P3b + (size_t)sId[j]*DD) + tid);
            float2 f0 = __half22float2(*(__half2*)&v.x);
            float2 f1 = __half22float2(*(__half2*)&v.y);
            float2 f2 = __half22float2(*(__half2*)&v.z);
            float2 f3 = __half22float2(*(__half2*)&v.w);
            acc[0] += wj*f0.x; acc[1] += wj*f0.y;
            acc[2] += wj*f1.x; acc[3] += wj*f1.y;
            acc[4] += wj*f2.x; acc[5] += wj*f2.y;
            acc[6] += wj*f3.x; acc[7] += wj*f3.y;
        }

        const int li = l / OHW, lj = l % OHW;
        const float* sall = d_sall + b*DD;
        #pragma unroll
        for (int q = 0; q < 8; q++) {
            int d = 8*tid + q;
            float val = (sall[d]*e0 + acc[q]) * invZ;
            int c = d / 49, rem = d % 49, ki = rem / 7, kj = rem % 7;
            int h = li*STR + ki, w = lj*STR + kj;
            atomicAdd(&d_out16[((size_t)(b*CI + c)*HH + h)*WW + w], val);
        }
    }
}

// ---------------- final: divide by analytic mask, restore conv ----------------
__device__ __forceinline__ int cover_count(int h) {
    int lo = h - 6; if (lo < 0) lo = 0;
    int hi = h;     if (hi > 120) hi = 120;
    return (hi >> 2) - ((lo + 3) >> 2) + 1;
}

__global__ void final_kernel(const float* __restrict__ mt_w, const float* __restrict__ mt_b,
                             const float* __restrict__ rs_w, const float* __restrict__ rs_b,
                             float* __restrict__ out) {
    __shared__ float rw[64][16];
    __shared__ float msum[16];
    __shared__ float mb[16];
    __shared__ float rb[64];

    const int tid = threadIdx.x;
    for (int i = tid; i < 1024; i += 256) rw[i/16][i%16] = rs_w[i];
    if (tid < 64) rb[tid] = rs_b[tid];
    if (tid < 16) {
        float s = 0.f;
        for (int c = 0; c < 64; c++) s += mt_w[tid*64 + c];
        msum[tid] = s;
        mb[tid]   = mt_b[tid];
    }
    __syncthreads();

    const int b = blockIdx.y;
    int pix = blockIdx.x*256 + tid;
    if (pix >= HH*WW) return;
    int h = pix / WW, w = pix % WW;
    float cnt = (float)(cover_count(h) * cover_count(w));

    float t[16];
    #pragma unroll
    for (int c = 0; c < 16; c++) {
        float v = d_out16[((size_t)(b*CI + c)*HH + h)*WW + w];
        t[c] = v / (cnt * msum[c] + mb[c] + 1e-8f);
    }
    #pragma unroll
    for (int o = 0; o < 64; o++) {
        float s = rb[o];
        #pragma unroll
        for (int c = 0; c < 16; c++) s += rw[o][c] * t[c];
        out[((size_t)(b*64 + o)*HH + h)*WW + w] = s;
    }
}

// ---------------- launch ------------------------------------------------------
extern "C" void kernel_launch(void* const* d_in, const int* in_sizes, int n_in,
                              void* d_out, int out_size) {
    const float* x    = (const float*)d_in[0];
    const float* g_w  = (const float*)d_in[1];
    const float* g_b  = (const float*)d_in[2];
    const float* th_w = (const float*)d_in[3];
    const float* th_b = (const float*)d_in[4];
    const float* ph_w = (const float*)d_in[5];
    const float* ph_b = (const float*)d_in[6];
    const float* mt_w = (const float*)d_in[7];
    const float* mt_b = (const float*)d_in[8];
    const float* rs_w = (const float*)d_in[9];
    const float* rs_b = (const float*)d_in[10];
    float* out = (float*)d_out;

    const int gemm_smem = 2*STAGE_B;   // 81920
    cudaFuncSetAttribute(score_gemm_mma, cudaFuncAttributeMaxDynamicSharedMemorySize, gemm_smem);

    zero16_kernel<<<512, 256>>>();
    conv_kernel<<<dim3(8,8,BB), dim3(16,16)>>>(x, g_w, g_b, th_w, th_b, ph_w, ph_b);
    {
        int total = BB*LP*KP;
        unfold_kernel<<<(total + 255)/256, 256>>>();
    }
    sall_kernel<<<dim3(4, 16, BB), 256>>>();
    score_gemm_mma<<<dim3(8, 8, BB), 256, gemm_smem>>>();
    topk_agg_kernel<<<dim3(LL, BB), 256>>>();
    final_kernel<<<dim3((HH*WW + 255)/256, BB), 256>>>(mt_w, mt_b, rs_w, rs_b, out);
}

// round 5
// speedup vs baseline: 2.3291x; 1.0089x over previous
#include <cuda_runtime.h>
#include <cuda_bf16.h>
#include <cuda_fp16.h>
#include <math.h>

#define HH 127
#define WW 127
#define CIN 64
#define CI  16
#define STR 4
#define OHW 31
#define LL  961           // 31*31
#define DD  784           // 16*49
#define BB  4
#define TOPM 100
#define LP 1024           // padded L
#define KP 832            // padded K (row stride of bf16 buffers)
#define NST 25            // 25 k-stages of 32 cover 800 >= 784
#define SP 964            // score row pitch (16B-aligned rows)

#define OPB 10240         // one operand tile in smem: 128 rows * 80B
#define STAGE_B (4*OPB)   // Ah, Al, Bh, Bl

// ---------------- scratch (device globals; no allocation allowed) ------------
__device__ float d_b1[BB*CI*HH*WW];
__device__ float d_b2[BB*CI*HH*WW];
__device__ float d_b3[BB*CI*HH*WW];
__device__ __nv_bfloat16 d_p1h[BB*LP*KP];
__device__ __nv_bfloat16 d_p1l[BB*LP*KP];
__device__ __nv_bfloat16 d_p2h[BB*LP*KP];
__device__ __nv_bfloat16 d_p2l[BB*LP*KP];
__device__ float  d_p3 [BB*LL*DD];
__device__ __half d_p3h[BB*LL*DD];
__device__ float d_score[BB*LL*SP];
__device__ float d_sall[BB*DD];
__device__ float d_out16[BB*CI*HH*WW];

// ---------------- PTX helpers --------------------------------------------------
__device__ __forceinline__ unsigned smem_u32(const void* p) {
    unsigned a;
    asm("{ .reg .u64 t; cvta.to.shared.u64 t, %1; cvt.u32.u64 %0, t; }" : "=r"(a) : "l"(p));
    return a;
}
__device__ __forceinline__ void cpa16(unsigned sdst, const void* gsrc) {
    asm volatile("cp.async.cg.shared.global [%0], [%1], 16;" :: "r"(sdst), "l"(gsrc));
}
#define CP_COMMIT() asm volatile("cp.async.commit_group;" ::: "memory")
#define CP_WAIT1()  asm volatile("cp.async.wait_group 1;" ::: "memory")

#define LDSM4(R, addr) \
    asm volatile("ldmatrix.sync.aligned.m8n8.x4.shared.b16 {%0,%1,%2,%3}, [%4];" \
        : "=r"((R)[0]),"=r"((R)[1]),"=r"((R)[2]),"=r"((R)[3]) : "r"(addr))

#define MMA16816(D, A, B0, B1) \
    asm volatile("mma.sync.aligned.m16n8k16.row.col.f32.bf16.bf16.f32 " \
        "{%0,%1,%2,%3}, {%4,%5,%6,%7}, {%8,%9}, {%0,%1,%2,%3};" \
        : "+f"((D)[0]),"+f"((D)[1]),"+f"((D)[2]),"+f"((D)[3]) \
        : "r"((A)[0]),"r"((A)[1]),"r"((A)[2]),"r"((A)[3]), "r"(B0),"r"(B1))

// ---------------- zero out16 + sall ------------------------------------------
__global__ void zero16_kernel() {
    int n = BB*CI*HH*WW;
    for (int i = blockIdx.x*blockDim.x + threadIdx.x; i < n; i += gridDim.x*blockDim.x)
        d_out16[i] = 0.f;
    int n2 = BB*DD;
    for (int i = blockIdx.x*blockDim.x + threadIdx.x; i < n2; i += gridDim.x*blockDim.x)
        d_sall[i] = 0.f;
}

// ---------------- fused conv3x3 (g) + conv1x1 (theta, phi) -------------------
__global__ void conv_kernel(const float* __restrict__ x,
                            const float* __restrict__ g_w,  const float* __restrict__ g_b,
                            const float* __restrict__ th_w, const float* __restrict__ th_b,
                            const float* __restrict__ ph_w, const float* __restrict__ ph_b) {
    __shared__ float xs[16][18][18];
    __shared__ float gw[16][16][9];
    __shared__ float tw[16][16];
    __shared__ float pw[16][16];

    const int b  = blockIdx.z;
    const int h0 = blockIdx.y * 16, w0 = blockIdx.x * 16;
    const int tx = threadIdx.x, ty = threadIdx.y;
    const int tid = ty*16 + tx;

    float ag[16], at[16], ap[16];
    #pragma unroll
    for (int c = 0; c < 16; c++) { ag[c]=0.f; at[c]=0.f; ap[c]=0.f; }

    const float* xb = x + (size_t)b*CIN*HH*WW;

    for (int c0 = 0; c0 < CIN; c0 += 16) {
        for (int i = tid; i < 16*18*18; i += 256) {
            int cc = i / 324;
            int rr = (i / 18) % 18;
            int col = i % 18;
            int hh = h0 - 1 + rr, ww2 = w0 - 1 + col;
            float v = 0.f;
            if (hh >= 0 && hh < HH && ww2 >= 0 && ww2 < WW)
                v = xb[(size_t)(c0+cc)*HH*WW + hh*WW + ww2];
            xs[cc][rr][col] = v;
        }
        for (int i = tid; i < 16*16*9; i += 256) {
            int co = i / 144, ci = (i / 9) % 16, kk = i % 9;
            gw[co][ci][kk] = g_w[((co*CIN) + (c0+ci))*9 + kk];
        }
        {
            int co = tid / 16, ci = tid % 16;
            tw[co][ci] = th_w[co*CIN + c0 + ci];
            pw[co][ci] = ph_w[co*CIN + c0 + ci];
        }
        __syncthreads();

        #pragma unroll 4
        for (int ci = 0; ci < 16; ci++) {
            float n0 = xs[ci][ty+0][tx+0], n1 = xs[ci][ty+0][tx+1], n2 = xs[ci][ty+0][tx+2];
            float n3 = xs[ci][ty+1][tx+0], n4 = xs[ci][ty+1][tx+1], n5 = xs[ci][ty+1][tx+2];
            float n6 = xs[ci][ty+2][tx+0], n7 = xs[ci][ty+2][tx+1], n8 = xs[ci][ty+2][tx+2];
            #pragma unroll
            for (int co = 0; co < 16; co++) {
                const float* wv = gw[co][ci];
                float s = wv[0]*n0 + wv[1]*n1 + wv[2]*n2
                        + wv[3]*n3 + wv[4]*n4 + wv[5]*n5
                        + wv[6]*n6 + wv[7]*n7 + wv[8]*n8;
                ag[co] += s;
                at[co] += tw[co][ci] * n4;
                ap[co] += pw[co][ci] * n4;
            }
        }
        __syncthreads();
    }

    int h = h0 + ty, w = w0 + tx;
    if (h < HH && w < WW) {
        #pragma unroll
        for (int co = 0; co < 16; co++) {
            size_t o = ((size_t)(b*CI + co)*HH + h)*WW + w;
            d_b1[o] = ag[co] + g_b[co];
            d_b2[o] = at[co] + th_b[co];
            d_b3[o] = ap[co] + ph_b[co];
        }
    }
}

// ---------------- unfold + bf16 split + fp16 copy + zero pads -----------------
__global__ void unfold_kernel() {
    const int total = BB*LP*KP;
    int i = blockIdx.x*blockDim.x + threadIdx.x;
    if (i >= total) return;
    int k = i % KP;
    int l = (i / KP) % LP;
    int b = i / (KP*LP);
    if (l < LL && k < DD) {
        int c = k / 49, rem = k % 49, ki = rem / 7, kj = rem % 7;
        int li = l / OHW, lj = l % OHW;
        int h = li*STR + ki, w = lj*STR + kj;
        size_t src = ((size_t)(b*CI + c)*HH + h)*WW + w;
        float v1 = d_b1[src], v2 = d_b2[src], v3 = d_b3[src];
        __nv_bfloat16 h1 = __float2bfloat16(v1);
        d_p1h[i] = h1;
        d_p1l[i] = __float2bfloat16(v1 - __bfloat162float(h1));
        __nv_bfloat16 h2 = __float2bfloat16(v2);
        d_p2h[i] = h2;
        d_p2l[i] = __float2bfloat16(v2 - __bfloat162float(h2));
        size_t pidx = ((size_t)b*LL + l)*DD + k;
        d_p3[pidx]  = v3;
        d_p3h[pidx] = __float2half_rn(v3);
    } else {
        __nv_bfloat16 z = __float2bfloat16(0.f);
        d_p1h[i] = z; d_p1l[i] = z; d_p2h[i] = z; d_p2l[i] = z;
    }
}

// ---------------- S_all: split-m 64 ways with atomics --------------------------
__global__ void sall_kernel() {
    int b = blockIdx.z;
    int d = blockIdx.x*blockDim.x + threadIdx.x;
    if (d >= DD) return;
    int m0 = blockIdx.y * 16;
    int m1 = m0 + 16; if (m1 > LL) m1 = LL;
    const float* base = d_p3 + (size_t)b*LL*DD + d;
    float s = 0.f;
    #pragma unroll 4
    for (int m = m0; m < m1; m++) s += base[(size_t)m*DD];
    atomicAdd(&d_sall[b*DD + d], s);
}

// ---------------- score = P1 @ P2^T via mma.sync bf16 3-split, fp32 accum -----
__global__ void __launch_bounds__(256, 2) score_gemm_mma() {
    extern __shared__ char smem[];
    const unsigned sb = smem_u32(smem);
    const int b = blockIdx.z;
    const int tmb = blockIdx.y * 128, tnb = blockIdx.x * 128;
    const int tid = threadIdx.x;
    const int wid = tid >> 5, lane = tid & 31;
    const int warp_m = wid >> 2;   // 0..1  -> m offset *64
    const int warp_n = wid & 3;    // 0..3  -> n offset *32

    const char* gops[4] = {
        (const char*)(d_p1h + (size_t)b*LP*KP + (size_t)tmb*KP),
        (const char*)(d_p1l + (size_t)b*LP*KP + (size_t)tmb*KP),
        (const char*)(d_p2h + (size_t)b*LP*KP + (size_t)tnb*KP),
        (const char*)(d_p2l + (size_t)b*LP*KP + (size_t)tnb*KP)
    };

    const unsigned aoff = (unsigned)((warp_m*64 + (lane & 15))*80 + (lane >> 4)*16);
    const unsigned boff = (unsigned)((warp_n*32 + (lane & 7) + ((lane >> 4) << 3))*80
                                     + ((lane >> 3) & 1)*16);

    float acc[4][4][4];
    #pragma unroll
    for (int i = 0; i < 4; i++)
        #pragma unroll
        for (int j = 0; j < 4; j++)
            #pragma unroll
            for (int q = 0; q < 4; q++) acc[i][j][q] = 0.f;

    #define LOAD_STAGE(s) do { \
        unsigned st_ = sb + ((s) & 1)*STAGE_B; \
        _Pragma("unroll") \
        for (int j_ = 0; j_ < 8; j_++) { \
            int idx_ = j_*256 + tid; \
            int op_ = idx_ >> 9, row_ = (idx_ >> 2) & 127, c_ = idx_ & 3; \
            cpa16(st_ + op_*OPB + row_*80 + c_*16, \
                  gops[op_] + (size_t)row_*(KP*2) + (size_t)(s)*64 + c_*16); \
        } \
    } while (0)

    LOAD_STAGE(0); CP_COMMIT();
    LOAD_STAGE(1); CP_COMMIT();

    for (int s = 0; s < NST; s++) {
        CP_WAIT1();
        __syncthreads();
        const unsigned stg = sb + (s & 1)*STAGE_B;

        #pragma unroll
        for (int k16 = 0; k16 < 2; k16++) {
            unsigned bh[8], bl[8];
            const unsigned bbase = stg + 2*OPB + boff + k16*32;
            LDSM4(bh + 0, bbase);
            LDSM4(bh + 4, bbase + 16*80);
            LDSM4(bl + 0, bbase + OPB);
            LDSM4(bl + 4, bbase + OPB + 16*80);

            #pragma unroll
            for (int mt = 0; mt < 4; mt++) {
                unsigned ah[4], al[4];
                const unsigned abase = stg + aoff + mt*(16*80) + k16*32;
                LDSM4(ah, abase);
                LDSM4(al, abase + OPB);
                #pragma unroll
                for (int nt = 0; nt < 4; nt++) {
                    MMA16816(acc[mt][nt], ah, bh[2*nt], bh[2*nt+1]);
                    MMA16816(acc[mt][nt], ah, bl[2*nt], bl[2*nt+1]);
                    MMA16816(acc[mt][nt], al, bh[2*nt], bh[2*nt+1]);
                }
            }
        }
        __syncthreads();
        if (s + 2 < NST) LOAD_STAGE(s + 2);
        CP_COMMIT();
    }

    #pragma unroll
    for (int mt = 0; mt < 4; mt++) {
        const int gm0 = tmb + warp_m*64 + mt*16 + (lane >> 2);
        #pragma unroll
        for (int nt = 0; nt < 4; nt++) {
            const int gn = tnb + warp_n*32 + nt*8 + (lane & 3)*2;
            const float* C = acc[mt][nt];
            if (gn < LL) {
                const bool two = (gn + 1 < LL);
                if (gm0 < LL) {
                    float* r = d_score + ((size_t)b*LL + gm0)*SP + gn;
                    r[0] = C[0];
                    if (two) r[1] = C[1];
                }
                if (gm0 + 8 < LL) {
                    float* r = d_score + ((size_t)b*LL + gm0 + 8)*SP + gn;
                    r[0] = C[2];
                    if (two) r[1] = C[3];
                }
            }
        }
    }
    #undef LOAD_STAGE
}

// ---------------- monotonic float<->key transform -----------------------------
__device__ __forceinline__ unsigned fkey(float f) {
    unsigned u = __float_as_uint(f);
    return u ^ (((int)u >> 31) | 0x80000000u);
}
__device__ __forceinline__ float funkey(unsigned k) {
    unsigned u = (k & 0x80000000u) ? (k ^ 0x80000000u) : ~k;
    return __uint_as_float(u);
}

// ---------------- per-row: radix-select top-100, softmax, gather, fold --------
__global__ void __launch_bounds__(256) topk_agg_kernel() {
    __shared__ unsigned keys[LL];
    __shared__ int hist[256];
    __shared__ int scn[256];
    __shared__ float red[256];
    __shared__ unsigned sKey[TOPM];
    __shared__ int sId[TOPM];
    __shared__ float se[TOPM];
    __shared__ float pacc[98*8];     // partial gather accs from j-half 1
    __shared__ unsigned prefix;
    __shared__ int kneed;
    __shared__ int cg, ce;

    const int l = blockIdx.x, b = blockIdx.y;
    const int tid = threadIdx.x;
    const float* row = d_score + ((size_t)b*LL + l)*SP;

    unsigned kmax = 0;
    #pragma unroll
    for (int r = 0; r < 4; r++) {
        int i = tid + r*256;
        if (i < LL) {
            unsigned k = fkey(row[i]);
            keys[i] = k;
            kmax = max(kmax, k);
        }
    }
    red[tid] = __uint_as_float(kmax);
    if (tid == 0) { prefix = 0; kneed = TOPM; cg = 0; ce = 0; }
    __syncthreads();
    #pragma unroll
    for (int s = 128; s > 0; s >>= 1) {
        if (tid < s) {
            unsigned a = __float_as_uint(red[tid]);
            unsigned c = __float_as_uint(red[tid + s]);
            red[tid] = __uint_as_float(a > c ? a : c);
        }
        __syncthreads();
    }
    const float vmax = funkey(__float_as_uint(red[0]));
    const float m = fmaxf(0.f, 10.f * vmax);
    __syncthreads();

    #pragma unroll
    for (int pass = 3; pass >= 0; pass--) {
        const int shift = pass * 8;
        const unsigned pm = (pass == 3) ? 0u : (0xFFFFFFFFu << (shift + 8));
        hist[tid] = 0;
        __syncthreads();
        unsigned pref = prefix;
        #pragma unroll
        for (int r = 0; r < 4; r++) {
            int i = tid + r*256;
            if (i < LL) {
                unsigned k = keys[i];
                if ((k & pm) == (pref & pm))
                    atomicAdd(&hist[(k >> shift) & 255], 1);
            }
        }
        __syncthreads();
        scn[tid] = hist[tid];
        __syncthreads();
        #pragma unroll
        for (int off = 1; off < 256; off <<= 1) {
            int v = (tid + off < 256) ? scn[tid + off] : 0;
            __syncthreads();
            scn[tid] += v;
            __syncthreads();
        }
        int kc = kneed;
        int gt = (tid < 255) ? scn[tid + 1] : 0;
        __syncthreads();
        if (scn[tid] >= kc && gt < kc) {
            prefix |= ((unsigned)tid) << shift;
            kneed = kc - gt;
        }
        __syncthreads();
    }

    const unsigned T = prefix;
    const int nTies = kneed;
    const int nGt = TOPM - nTies;

    #pragma unroll
    for (int r = 0; r < 4; r++) {
        int i = tid + r*256;
        if (i < LL) {
            unsigned k = keys[i];
            if (k > T) {
                int p = atomicAdd(&cg, 1);
                sKey[p] = k; sId[p] = i;
            } else if (k == T) {
                int q = atomicAdd(&ce, 1);
                if (q < nTies) {
                    sKey[nGt + q] = k; sId[nGt + q] = i;
                }
            }
        }
    }
    __syncthreads();

    float myE = 0.f;
    if (tid < TOPM) {
        myE = expf(10.f * funkey(sKey[tid]) - m);
        se[tid] = myE;
    }
    red[tid] = myE;
    __syncthreads();
    #pragma unroll
    for (int s = 128; s > 0; s >>= 1) {
        if (tid < s) red[tid] += red[tid + s];
        __syncthreads();
    }
    const float e0   = expf(-m);
    const float Z    = red[0] + (float)(LL - TOPM) * e0;
    const float invZ = 1.f / Z;

    // gather-GEMM over fp16 p3: 196 threads, j-loop split in two halves of 50
    float acc[8];
    #pragma unroll
    for (int q = 0; q < 8; q++) acc[q] = 0.f;
    const int chunk = (tid < 98) ? tid : tid - 98;    // uint4 index in row
    const int jh    = (tid < 98) ? 0 : 1;
    if (tid < 196) {
        const __half* P3b = d_p3h + (size_t)b*LL*DD;
        const int j0 = jh * 50;
        #pragma unroll 2
        for (int j = j0; j < j0 + 50; j++) {
            float wj = se[j] - e0;
            uint4 v = *((const uint4*)(P3b + (size_t)sId[j]*DD) + chunk);
            float2 f0 = __half22float2(*(__half2*)&v.x);
            float2 f1 = __half22float2(*(__half2*)&v.y);
            float2 f2 = __half22float2(*(__half2*)&v.z);
            float2 f3 = __half22float2(*(__half2*)&v.w);
            acc[0] += wj*f0.x; acc[1] += wj*f0.y;
            acc[2] += wj*f1.x; acc[3] += wj*f1.y;
            acc[4] += wj*f2.x; acc[5] += wj*f2.y;
            acc[6] += wj*f3.x; acc[7] += wj*f3.y;
        }
        if (jh == 1) {
            #pragma unroll
            for (int q = 0; q < 8; q++) pacc[chunk*8 + q] = acc[q];
        }
    }
    __syncthreads();

    if (tid < 98) {
        const int li = l / OHW, lj = l % OHW;
        const float* sall = d_sall + b*DD;
        #pragma unroll
        for (int q = 0; q < 8; q++) {
            int d = 8*tid + q;
            float val = (sall[d]*e0 + acc[q] + pacc[tid*8 + q]) * invZ;
            int c = d / 49, rem = d % 49, ki = rem / 7, kj = rem % 7;
            int h = li*STR + ki, w = lj*STR + kj;
            atomicAdd(&d_out16[((size_t)(b*CI + c)*HH + h)*WW + w], val);
        }
    }
}

// ---------------- final: divide by analytic mask, restore conv ----------------
__device__ __forceinline__ int cover_count(int h) {
    int lo = h - 6; if (lo < 0) lo = 0;
    int hi = h;     if (hi > 120) hi = 120;
    return (hi >> 2) - ((lo + 3) >> 2) + 1;
}

__global__ void final_kernel(const float* __restrict__ mt_w, const float* __restrict__ mt_b,
                             const float* __restrict__ rs_w, const float* __restrict__ rs_b,
                             float* __restrict__ out) {
    __shared__ float rw[64][16];
    __shared__ float msum[16];
    __shared__ float mb[16];
    __shared__ float rb[64];

    const int tid = threadIdx.x;
    for (int i = tid; i < 1024; i += 256) rw[i/16][i%16] = rs_w[i];
    if (tid < 64) rb[tid] = rs_b[tid];
    if (tid < 16) {
        float s = 0.f;
        for (int c = 0; c < 64; c++) s += mt_w[tid*64 + c];
        msum[tid] = s;
        mb[tid]   = mt_b[tid];
    }
    __syncthreads();

    const int b = blockIdx.y;
    int pix = blockIdx.x*256 + tid;
    if (pix >= HH*WW) return;
    int h = pix / WW, w = pix % WW;
    float cnt = (float)(cover_count(h) * cover_count(w));

    float t[16];
    #pragma unroll
    for (int c = 0; c < 16; c++) {
        float v = d_out16[((size_t)(b*CI + c)*HH + h)*WW + w];
        t[c] = v / (cnt * msum[c] + mb[c] + 1e-8f);
    }
    #pragma unroll
    for (int o = 0; o < 64; o++) {
        float s = rb[o];
        #pragma unroll
        for (int c = 0; c < 16; c++) s += rw[o][c] * t[c];
        out[((size_t)(b*64 + o)*HH + h)*WW + w] = s;
    }
}

// ---------------- launch ------------------------------------------------------
extern "C" void kernel_launch(void* const* d_in, const int* in_sizes, int n_in,
                              void* d_out, int out_size) {
    const float* x    = (const float*)d_in[0];
    const float* g_w  = (const float*)d_in[1];
    const float* g_b  = (const float*)d_in[2];
    const float* th_w = (const float*)d_in[3];
    const float* th_b = (const float*)d_in[4];
    const float* ph_w = (const float*)d_in[5];
    const float* ph_b = (const float*)d_in[6];
    const float* mt_w = (const float*)d_in[7];
    const float* mt_b = (const float*)d_in[8];
    const float* rs_w = (const float*)d_in[9];
    const float* rs_b = (const float*)d_in[10];
    float* out = (float*)d_out;

    const int gemm_smem = 2*STAGE_B;   // 81920
    cudaFuncSetAttribute(score_gemm_mma, cudaFuncAttributeMaxDynamicSharedMemorySize, gemm_smem);

    zero16_kernel<<<512, 256>>>();
    conv_kernel<<<dim3(8,8,BB), dim3(16,16)>>>(x, g_w, g_b, th_w, th_b, ph_w, ph_b);
    {
        int total = BB*LP*KP;
        unfold_kernel<<<(total + 255)/256, 256>>>();
    }
    sall_kernel<<<dim3(4, 61, BB), 256>>>();
    score_gemm_mma<<<dim3(8, 8, BB), 256, gemm_smem>>>();
    topk_agg_kernel<<<dim3(LL, BB), 256>>>();
    final_kernel<<<dim3((HH*WW + 255)/256, BB), 256>>>(mt_w, mt_b, rs_w, rs_b, out);
}

// round 6
// speedup vs baseline: 2.5215x; 1.0826x over previous
#include <cuda_runtime.h>
#include <cuda_bf16.h>
#include <cuda_fp16.h>
#include <math.h>

#define HH 127
#define WW 127
#define CIN 64
#define CI  16
#define STR 4
#define OHW 31
#define LL  961           // 31*31
#define DD  784           // 16*49
#define BB  4
#define TOPM 100
#define LP 1024           // padded L
#define KP 832            // padded K (row stride of bf16 buffers)
#define NST 25            // 25 k-stages of 32 cover 800 >= 784
#define SP 964            // score row pitch (16B-aligned rows)

#define OPB 10240         // one operand tile in smem: 128 rows * 80B
#define STAGE_B (4*OPB)   // Ah, Al, Bh, Bl

// ---------------- scratch (device globals; no allocation allowed) ------------
__device__ float d_b1[BB*CI*HH*WW];
__device__ float d_b2[BB*CI*HH*WW];
__device__ float d_b3[BB*CI*HH*WW];
__device__ __nv_bfloat16 d_p1h[BB*LP*KP];
__device__ __nv_bfloat16 d_p1l[BB*LP*KP];
__device__ __nv_bfloat16 d_p2h[BB*LP*KP];
__device__ __nv_bfloat16 d_p2l[BB*LP*KP];
__device__ float  d_p3 [BB*LL*DD];
__device__ __half d_p3h[BB*LL*DD];
__device__ float d_score[BB*LL*SP];
__device__ float d_sall[BB*DD];
__device__ float d_out16[BB*CI*HH*WW];

// ---------------- PTX helpers --------------------------------------------------
__device__ __forceinline__ unsigned smem_u32(const void* p) {
    unsigned a;
    asm("{ .reg .u64 t; cvta.to.shared.u64 t, %1; cvt.u32.u64 %0, t; }" : "=r"(a) : "l"(p));
    return a;
}
__device__ __forceinline__ void cpa16(unsigned sdst, const void* gsrc) {
    asm volatile("cp.async.cg.shared.global [%0], [%1], 16;" :: "r"(sdst), "l"(gsrc));
}
#define CP_COMMIT() asm volatile("cp.async.commit_group;" ::: "memory")
#define CP_WAIT1()  asm volatile("cp.async.wait_group 1;" ::: "memory")

#define LDSM4(R, addr) \
    asm volatile("ldmatrix.sync.aligned.m8n8.x4.shared.b16 {%0,%1,%2,%3}, [%4];" \
        : "=r"((R)[0]),"=r"((R)[1]),"=r"((R)[2]),"=r"((R)[3]) : "r"(addr))

#define MMA16816(D, A, B0, B1) \
    asm volatile("mma.sync.aligned.m16n8k16.row.col.f32.bf16.bf16.f32 " \
        "{%0,%1,%2,%3}, {%4,%5,%6,%7}, {%8,%9}, {%0,%1,%2,%3};" \
        : "+f"((D)[0]),"+f"((D)[1]),"+f"((D)[2]),"+f"((D)[3]) \
        : "r"((A)[0]),"r"((A)[1]),"r"((A)[2]),"r"((A)[3]), "r"(B0),"r"(B1))

// ---------------- zero out16 + sall ------------------------------------------
__global__ void zero16_kernel() {
    int n = BB*CI*HH*WW;
    for (int i = blockIdx.x*blockDim.x + threadIdx.x; i < n; i += gridDim.x*blockDim.x)
        d_out16[i] = 0.f;
    int n2 = BB*DD;
    for (int i = blockIdx.x*blockDim.x + threadIdx.x; i < n2; i += gridDim.x*blockDim.x)
        d_sall[i] = 0.f;
}

// ---------------- fused conv3x3 (g) + conv1x1 (theta, phi) -------------------
// Thread = (co = tx, pixel-row = ty), computes 16 pixel columns.
// Weights register-cached per (co,ci); input rows broadcast from smem.
__global__ void conv_kernel(const float* __restrict__ x,
                            const float* __restrict__ g_w,  const float* __restrict__ g_b,
                            const float* __restrict__ th_w, const float* __restrict__ th_b,
                            const float* __restrict__ ph_w, const float* __restrict__ ph_b) {
    __shared__ float xs[16][18][18];
    __shared__ float gw[16][16][9];
    __shared__ float tw[16][16];
    __shared__ float pw[16][16];

    const int b  = blockIdx.z;
    const int h0 = blockIdx.y * 16, w0 = blockIdx.x * 16;
    const int tx = threadIdx.x, ty = threadIdx.y;
    const int tid = ty*16 + tx;
    const int co = tx, row = ty;

    float ag[16], at[16], ap[16];
    #pragma unroll
    for (int c = 0; c < 16; c++) { ag[c]=0.f; at[c]=0.f; ap[c]=0.f; }

    const float* xb = x + (size_t)b*CIN*HH*WW;

    for (int c0 = 0; c0 < CIN; c0 += 16) {
        for (int i = tid; i < 16*18*18; i += 256) {
            int cc = i / 324;
            int rr = (i / 18) % 18;
            int col = i % 18;
            int hh = h0 - 1 + rr, ww2 = w0 - 1 + col;
            float v = 0.f;
            if (hh >= 0 && hh < HH && ww2 >= 0 && ww2 < WW)
                v = xb[(size_t)(c0+cc)*HH*WW + hh*WW + ww2];
            xs[cc][rr][col] = v;
        }
        for (int i = tid; i < 16*16*9; i += 256) {
            int o = i / 144, ci = (i / 9) % 16, kk = i % 9;
            gw[o][ci][kk] = g_w[((o*CIN) + (c0+ci))*9 + kk];
        }
        {
            int o = tid / 16, ci = tid % 16;
            tw[o][ci] = th_w[o*CIN + c0 + ci];
            pw[o][ci] = ph_w[o*CIN + c0 + ci];
        }
        __syncthreads();

        for (int ci = 0; ci < 16; ci++) {
            float wv[9];
            #pragma unroll
            for (int j = 0; j < 9; j++) wv[j] = gw[co][ci][j];
            const float tws = tw[co][ci], pws = pw[co][ci];

            #pragma unroll
            for (int ki = 0; ki < 3; ki++) {
                float rv[18];
                #pragma unroll
                for (int j = 0; j < 18; j++) rv[j] = xs[ci][row+ki][j];
                #pragma unroll
                for (int c = 0; c < 16; c++) {
                    float s = ag[c];
                    s = fmaf(wv[3*ki+0], rv[c],   s);
                    s = fmaf(wv[3*ki+1], rv[c+1], s);
                    s = fmaf(wv[3*ki+2], rv[c+2], s);
                    ag[c] = s;
                }
                if (ki == 1) {
                    #pragma unroll
                    for (int c = 0; c < 16; c++) {
                        at[c] = fmaf(tws, rv[c+1], at[c]);
                        ap[c] = fmaf(pws, rv[c+1], ap[c]);
                    }
                }
            }
        }
        __syncthreads();
    }

    const int h = h0 + row;
    if (h < HH) {
        const float gb = g_b[co], tb = th_b[co], pb = ph_b[co];
        size_t baseo = ((size_t)(b*CI + co)*HH + h)*WW + w0;
        #pragma unroll
        for (int c = 0; c < 16; c++) {
            if (w0 + c < WW) {
                d_b1[baseo + c] = ag[c] + gb;
                d_b2[baseo + c] = at[c] + tb;
                d_b3[baseo + c] = ap[c] + pb;
            }
        }
    }
}

// ---------------- unfold + bf16 split + fp16 copy + zero pads -----------------
__global__ void unfold_kernel() {
    const int total = BB*LP*KP;
    int i = blockIdx.x*blockDim.x + threadIdx.x;
    if (i >= total) return;
    int k = i % KP;
    int l = (i / KP) % LP;
    int b = i / (KP*LP);
    if (l < LL && k < DD) {
        int c = k / 49, rem = k % 49, ki = rem / 7, kj = rem % 7;
        int li = l / OHW, lj = l % OHW;
        int h = li*STR + ki, w = lj*STR + kj;
        size_t src = ((size_t)(b*CI + c)*HH + h)*WW + w;
        float v1 = d_b1[src], v2 = d_b2[src], v3 = d_b3[src];
        __nv_bfloat16 h1 = __float2bfloat16(v1);
        d_p1h[i] = h1;
        d_p1l[i] = __float2bfloat16(v1 - __bfloat162float(h1));
        __nv_bfloat16 h2 = __float2bfloat16(v2);
        d_p2h[i] = h2;
        d_p2l[i] = __float2bfloat16(v2 - __bfloat162float(h2));
        size_t pidx = ((size_t)b*LL + l)*DD + k;
        d_p3[pidx]  = v3;
        d_p3h[pidx] = __float2half_rn(v3);
    } else {
        __nv_bfloat16 z = __float2bfloat16(0.f);
        d_p1h[i] = z; d_p1l[i] = z; d_p2h[i] = z; d_p2l[i] = z;
    }
}

// ---------------- S_all: split-m 61 ways with atomics --------------------------
__global__ void sall_kernel() {
    int b = blockIdx.z;
    int d = blockIdx.x*blockDim.x + threadIdx.x;
    if (d >= DD) return;
    int m0 = blockIdx.y * 16;
    int m1 = m0 + 16; if (m1 > LL) m1 = LL;
    const float* base = d_p3 + (size_t)b*LL*DD + d;
    float s = 0.f;
    #pragma unroll 4
    for (int m = m0; m < m1; m++) s += base[(size_t)m*DD];
    atomicAdd(&d_sall[b*DD + d], s);
}

// ---------------- score = P1 @ P2^T via mma.sync bf16 3-split, fp32 accum -----
__global__ void __launch_bounds__(256, 2) score_gemm_mma() {
    extern __shared__ char smem[];
    const unsigned sb = smem_u32(smem);
    const int b = blockIdx.z;
    const int tmb = blockIdx.y * 128, tnb = blockIdx.x * 128;
    const int tid = threadIdx.x;
    const int wid = tid >> 5, lane = tid & 31;
    const int warp_m = wid >> 2;
    const int warp_n = wid & 3;

    const char* gops[4] = {
        (const char*)(d_p1h + (size_t)b*LP*KP + (size_t)tmb*KP),
        (const char*)(d_p1l + (size_t)b*LP*KP + (size_t)tmb*KP),
        (const char*)(d_p2h + (size_t)b*LP*KP + (size_t)tnb*KP),
        (const char*)(d_p2l + (size_t)b*LP*KP + (size_t)tnb*KP)
    };

    const unsigned aoff = (unsigned)((warp_m*64 + (lane & 15))*80 + (lane >> 4)*16);
    const unsigned boff = (unsigned)((warp_n*32 + (lane & 7) + ((lane >> 4) << 3))*80
                                     + ((lane >> 3) & 1)*16);

    float acc[4][4][4];
    #pragma unroll
    for (int i = 0; i < 4; i++)
        #pragma unroll
        for (int j = 0; j < 4; j++)
            #pragma unroll
            for (int q = 0; q < 4; q++) acc[i][j][q] = 0.f;

    #define LOAD_STAGE(s) do { \
        unsigned st_ = sb + ((s) & 1)*STAGE_B; \
        _Pragma("unroll") \
        for (int j_ = 0; j_ < 8; j_++) { \
            int idx_ = j_*256 + tid; \
            int op_ = idx_ >> 9, row_ = (idx_ >> 2) & 127, c_ = idx_ & 3; \
            cpa16(st_ + op_*OPB + row_*80 + c_*16, \
                  gops[op_] + (size_t)row_*(KP*2) + (size_t)(s)*64 + c_*16); \
        } \
    } while (0)

    LOAD_STAGE(0); CP_COMMIT();
    LOAD_STAGE(1); CP_COMMIT();

    for (int s = 0; s < NST; s++) {
        CP_WAIT1();
        __syncthreads();
        const unsigned stg = sb + (s & 1)*STAGE_B;

        #pragma unroll
        for (int k16 = 0; k16 < 2; k16++) {
            unsigned bh[8], bl[8];
            const unsigned bbase = stg + 2*OPB + boff + k16*32;
            LDSM4(bh + 0, bbase);
            LDSM4(bh + 4, bbase + 16*80);
            LDSM4(bl + 0, bbase + OPB);
            LDSM4(bl + 4, bbase + OPB + 16*80);

            #pragma unroll
            for (int mt = 0; mt < 4; mt++) {
                unsigned ah[4], al[4];
                const unsigned abase = stg + aoff + mt*(16*80) + k16*32;
                LDSM4(ah, abase);
                LDSM4(al, abase + OPB);
                #pragma unroll
                for (int nt = 0; nt < 4; nt++) {
                    MMA16816(acc[mt][nt], ah, bh[2*nt], bh[2*nt+1]);
                    MMA16816(acc[mt][nt], ah, bl[2*nt], bl[2*nt+1]);
                    MMA16816(acc[mt][nt], al, bh[2*nt], bh[2*nt+1]);
                }
            }
        }
        __syncthreads();
        if (s + 2 < NST) LOAD_STAGE(s + 2);
        CP_COMMIT();
    }

    #pragma unroll
    for (int mt = 0; mt < 4; mt++) {
        const int gm0 = tmb + warp_m*64 + mt*16 + (lane >> 2);
        #pragma unroll
        for (int nt = 0; nt < 4; nt++) {
            const int gn = tnb + warp_n*32 + nt*8 + (lane & 3)*2;
            const float* C = acc[mt][nt];
            if (gn < LL) {
                const bool two = (gn + 1 < LL);
                if (gm0 < LL) {
                    float* r = d_score + ((size_t)b*LL + gm0)*SP + gn;
                    r[0] = C[0];
                    if (two) r[1] = C[1];
                }
                if (gm0 + 8 < LL) {
                    float* r = d_score + ((size_t)b*LL + gm0 + 8)*SP + gn;
                    r[0] = C[2];
                    if (two) r[1] = C[3];
                }
            }
        }
    }
    #undef LOAD_STAGE
}

// ---------------- monotonic float<->key transform -----------------------------
__device__ __forceinline__ unsigned fkey(float f) {
    unsigned u = __float_as_uint(f);
    return u ^ (((int)u >> 31) | 0x80000000u);
}
__device__ __forceinline__ float funkey(unsigned k) {
    unsigned u = (k & 0x80000000u) ? (k ^ 0x80000000u) : ~k;
    return __uint_as_float(u);
}

// ---------------- per-row: 2-pass radix select, softmax, gather, fold ---------
__global__ void __launch_bounds__(256) topk_agg_kernel() {
    __shared__ unsigned keys[LL];
    __shared__ int candId[LL];
    __shared__ int hist[256];
    __shared__ int scn[257];
    __shared__ int wsum[8];
    __shared__ float red[256];
    __shared__ unsigned sKey[TOPM];
    __shared__ int sId[TOPM];
    __shared__ float se[TOPM];
    __shared__ float pacc[98*8];
    __shared__ int sDigit, sKneed;
    __shared__ int cg, ce;

    const int l = blockIdx.x, b = blockIdx.y;
    const int tid = threadIdx.x;
    const int lane = tid & 31;
    const float* row = d_score + ((size_t)b*LL + l)*SP;

    unsigned kmax = 0;
    #pragma unroll
    for (int r = 0; r < 4; r++) {
        int i = tid + r*256;
        if (i < LL) {
            unsigned k = fkey(row[i]);
            keys[i] = k;
            kmax = max(kmax, k);
        }
    }
    red[tid] = __uint_as_float(kmax);
    if (tid == 0) { sKneed = TOPM; cg = 0; ce = 0; }
    __syncthreads();
    #pragma unroll
    for (int s = 128; s > 0; s >>= 1) {
        if (tid < s) {
            unsigned a = __float_as_uint(red[tid]);
            unsigned c = __float_as_uint(red[tid + s]);
            red[tid] = __uint_as_float(a > c ? a : c);
        }
        __syncthreads();
    }
    const float vmax = funkey(__float_as_uint(red[0]));
    const float m = fmaxf(0.f, 10.f * vmax);
    __syncthreads();

    // ---- 2-pass radix select on top 16 key bits ----
    int d1 = -1;   // chosen top byte (kept per-thread after pass 1 via shared)
    #pragma unroll
    for (int pass = 0; pass < 2; pass++) {
        hist[tid] = 0;
        __syncthreads();
        const int shift = pass ? 16 : 24;
        const int pd1 = pass ? sDigit : -1;
        #pragma unroll
        for (int r = 0; r < 4; r++) {
            int i = tid + r*256;
            int dg = 0x10000;       // sentinel (invalid)
            if (i < LL) {
                unsigned k = keys[i];
                if (!pass || (int)(k >> 24) == pd1)
                    dg = (int)((k >> shift) & 255);
            }
            unsigned mg = __match_any_sync(0xffffffffu, dg);
            if (lane == __ffs(mg) - 1 && dg != 0x10000)
                atomicAdd(&hist[dg], __popc(mg));
        }
        __syncthreads();
        // suffix scan: scn[bn] = sum_{j>=bn} hist[j]
        {
            int rb = 255 - tid;
            int v = hist[rb];
            #pragma unroll
            for (int off = 1; off < 32; off <<= 1) {
                int n = __shfl_up_sync(0xffffffffu, v, off);
                if (lane >= off) v += n;
            }
            if (lane == 31) wsum[tid >> 5] = v;
            __syncthreads();
            if (tid < 8) {
                int s2 = wsum[tid];
                #pragma unroll
                for (int off = 1; off < 8; off <<= 1) {
                    int n = __shfl_up_sync(0xffu, s2, off);
                    if (tid >= off) s2 += n;
                }
                wsum[tid] = s2;
            }
            __syncthreads();
            int addv = (tid >= 32) ? wsum[(tid >> 5) - 1] : 0;
            scn[rb] = v + addv;
            if (tid == 0) scn[256] = 0;
        }
        __syncthreads();
        int kc = sKneed;
        int ge = scn[tid], gt = scn[tid + 1];
        __syncthreads();
        if (ge >= kc && gt < kc) { sDigit = tid; sKneed = kc - gt; }
        __syncthreads();
        if (!pass) d1 = sDigit;
    }

    const unsigned T16 = ((unsigned)d1 << 8) | (unsigned)sDigit;
    const int kneedF = sKneed;
    const int nGt = TOPM - kneedF;

    // collect: strictly greater (16-bit) directly; ties into candidate list
    #pragma unroll
    for (int r = 0; r < 4; r++) {
        int i = tid + r*256;
        if (i < LL) {
            unsigned k16 = keys[i] >> 16;
            if (k16 > T16) {
                int p = atomicAdd(&cg, 1);
                sKey[p] = keys[i]; sId[p] = i;
            } else if (k16 == T16) {
                int q = atomicAdd(&ce, 1);
                candId[q] = i;
            }
        }
    }
    __syncthreads();

    // tie resolution by full 32-bit (key, index) rank
    {
        const int nc = ce;
        for (int t = tid; t < nc; t += 256) {
            const int  myI = candId[t];
            const unsigned mk = keys[myI];
            int rank = 0;
            for (int j = 0; j < nc; j++) {
                unsigned kj = keys[candId[j]];
                rank += (kj > mk) || (kj == mk && j < t);
            }
            if (rank < kneedF) { sKey[nGt + rank] = mk; sId[nGt + rank] = myI; }
        }
    }
    __syncthreads();

    float myE = 0.f;
    if (tid < TOPM) {
        myE = expf(10.f * funkey(sKey[tid]) - m);
        se[tid] = myE;
    }
    red[tid] = myE;
    __syncthreads();
    #pragma unroll
    for (int s = 128; s > 0; s >>= 1) {
        if (tid < s) red[tid] += red[tid + s];
        __syncthreads();
    }
    const float e0   = expf(-m);
    const float Z    = red[0] + (float)(LL - TOPM) * e0;
    const float invZ = 1.f / Z;

    // gather-GEMM over fp16 p3: 196 threads, j-loop split in two halves of 50
    float acc[8];
    #pragma unroll
    for (int q = 0; q < 8; q++) acc[q] = 0.f;
    const int chunk = (tid < 98) ? tid : tid - 98;
    const int jh    = (tid < 98) ? 0 : 1;
    if (tid < 196) {
        const __half* P3b = d_p3h + (size_t)b*LL*DD;
        const int j0 = jh * 50;
        #pragma unroll 2
        for (int j = j0; j < j0 + 50; j++) {
            float wj = se[j] - e0;
            uint4 v = *((const uint4*)(P3b + (size_t)sId[j]*DD) + chunk);
            float2 f0 = __half22float2(*(__half2*)&v.x);
            float2 f1 = __half22float2(*(__half2*)&v.y);
            float2 f2 = __half22float2(*(__half2*)&v.z);
            float2 f3 = __half22float2(*(__half2*)&v.w);
            acc[0] += wj*f0.x; acc[1] += wj*f0.y;
            acc[2] += wj*f1.x; acc[3] += wj*f1.y;
            acc[4] += wj*f2.x; acc[5] += wj*f2.y;
            acc[6] += wj*f3.x; acc[7] += wj*f3.y;
        }
        if (jh == 1) {
            #pragma unroll
            for (int q = 0; q < 8; q++) pacc[chunk*8 + q] = acc[q];
        }
    }
    __syncthreads();

    if (tid < 98) {
        const int li = l / OHW, lj = l % OHW;
        const float* sall = d_sall + b*DD;
        #pragma unroll
        for (int q = 0; q < 8; q++) {
            int d = 8*tid + q;
            float val = (sall[d]*e0 + acc[q] + pacc[tid*8 + q]) * invZ;
            int c = d / 49, rem = d % 49, ki = rem / 7, kj = rem % 7;
            int h = li*STR + ki, w = lj*STR + kj;
            atomicAdd(&d_out16[((size_t)(b*CI + c)*HH + h)*WW + w], val);
        }
    }
}

// ---------------- final: divide by analytic mask, restore conv ----------------
__device__ __forceinline__ int cover_count(int h) {
    int lo = h - 6; if (lo < 0) lo = 0;
    int hi = h;     if (hi > 120) hi = 120;
    return (hi >> 2) - ((lo + 3) >> 2) + 1;
}

__global__ void final_kernel(const float* __restrict__ mt_w, const float* __restrict__ mt_b,
                             const float* __restrict__ rs_w, const float* __restrict__ rs_b,
                             float* __restrict__ out) {
    __shared__ float rw[64][16];
    __shared__ float msum[16];
    __shared__ float mb[16];
    __shared__ float rb[64];

    const int tid = threadIdx.x;
    for (int i = tid; i < 1024; i += 256) rw[i/16][i%16] = rs_w[i];
    if (tid < 64) rb[tid] = rs_b[tid];
    if (tid < 16) {
        float s = 0.f;
        for (int c = 0; c < 64; c++) s += mt_w[tid*64 + c];
        msum[tid] = s;
        mb[tid]   = mt_b[tid];
    }
    __syncthreads();

    const int b = blockIdx.y;
    int pix = blockIdx.x*256 + tid;
    if (pix >= HH*WW) return;
    int h = pix / WW, w = pix % WW;
    float cnt = (float)(cover_count(h) * cover_count(w));

    float t[16];
    #pragma unroll
    for (int c = 0; c < 16; c++) {
        float v = d_out16[((size_t)(b*CI + c)*HH + h)*WW + w];
        t[c] = v / (cnt * msum[c] + mb[c] + 1e-8f);
    }
    #pragma unroll
    for (int o = 0; o < 64; o++) {
        float s = rb[o];
        #pragma unroll
        for (int c = 0; c < 16; c++) s += rw[o][c] * t[c];
        out[((size_t)(b*64 + o)*HH + h)*WW + w] = s;
    }
}

// ---------------- launch ------------------------------------------------------
extern "C" void kernel_launch(void* const* d_in, const int* in_sizes, int n_in,
                              void* d_out, int out_size) {
    const float* x    = (const float*)d_in[0];
    const float* g_w  = (const float*)d_in[1];
    const float* g_b  = (const float*)d_in[2];
    const float* th_w = (const float*)d_in[3];
    const float* th_b = (const float*)d_in[4];
    const float* ph_w = (const float*)d_in[5];
    const float* ph_b = (const float*)d_in[6];
    const float* mt_w = (const float*)d_in[7];
    const float* mt_b = (const float*)d_in[8];
    const float* rs_w = (const float*)d_in[9];
    const float* rs_b = (const float*)d_in[10];
    float* out = (float*)d_out;

    const int gemm_smem = 2*STAGE_B;   // 81920
    cudaFuncSetAttribute(score_gemm_mma, cudaFuncAttributeMaxDynamicSharedMemorySize, gemm_smem);

    zero16_kernel<<<512, 256>>>();
    conv_kernel<<<dim3(8,8,BB), dim3(16,16)>>>(x, g_w, g_b, th_w, th_b, ph_w, ph_b);
    {
        int total = BB*LP*KP;
        unfold_kernel<<<(total + 255)/256, 256>>>();
    }
    sall_kernel<<<dim3(4, 61, BB), 256>>>();
    score_gemm_mma<<<dim3(8, 8, BB), 256, gemm_smem>>>();
    topk_agg_kernel<<<dim3(LL, BB), 256>>>();
    final_kernel<<<dim3((HH*WW + 255)/256, BB), 256>>>(mt_w, mt_b, rs_w, rs_b, out);
}